// round 4
// baseline (speedup 1.0000x reference)
#include <cuda_runtime.h>
#include <cuda_bf16.h>
#include <math.h>
#include <stdint.h>

// ---------------- problem constants ----------------
#define NB 4
#define SS 1024
#define DD 1536
#define NH 12
#define HDIM 128
#define MAXC 256
#define SM1 1023
#define ROWS_DET (NB*SM1)        // 4092
#define CS_TOT (1023+511+255)    // 1789

// ---------------- fp32 scratch ----------------
__device__ float g_xling[(size_t)NB*SS*DD];
__device__ float g_norm[NB*SS];
__device__ float g_cs[NB*CS_TOT];
__device__ float g_base[NB*SM1];
__device__ float g_h2[(size_t)3*ROWS_DET*(DD/2)];
__device__ float g_final[NB*SM1];
__device__ int   g_seg[NB*SS];
__device__ int   g_segstart[NB*MAXC];
__device__ int   g_segcount[NB*MAXC];
__device__ float g_qkv[(size_t)NB*SS*3*DD];
__device__ float g_scores[(size_t)NB*NH*SS*SS];
__device__ float g_attnout[(size_t)NB*SS*DD];
__device__ float g_y[(size_t)NB*MAXC*DD];

// ---------------- bf16 split scratch ----------------
__device__ __nv_bfloat16 g_x3[(size_t)NB*SS*3*DD];
__device__ __nv_bfloat16 g_Wp3[(size_t)DD*3*DD];
__device__ __nv_bfloat16 g_bi3[(size_t)ROWS_DET*3*(2*DD)];
__device__ __nv_bfloat16 g_detW1_3[(size_t)3*DD*3*(2*DD)];
__device__ __nv_bfloat16 g_h1_3[(size_t)3*ROWS_DET*3*DD];
__device__ __nv_bfloat16 g_detW2_3[(size_t)3*(DD/2)*3*DD];
__device__ __nv_bfloat16 g_wqkv3[(size_t)3*DD*3*DD];
__device__ __nv_bfloat16 g_ctx3[(size_t)NB*SS*3*DD];
__device__ __nv_bfloat16 g_outw3[(size_t)DD*3*DD];
__device__ __nv_bfloat16 g_chunk3[(size_t)NB*MAXC*3*DD];
__device__ __nv_bfloat16 g_pw1_3[(size_t)2*DD*3*DD];
__device__ __nv_bfloat16 g_hproc3[(size_t)NB*MAXC*3*2*DD];
__device__ __nv_bfloat16 g_pw2_3[(size_t)DD*3*2*DD];
__device__ __nv_bfloat16 g_q2[(size_t)NB*NH*SS*2*HDIM];
__device__ __nv_bfloat16 g_k2[(size_t)NB*NH*SS*2*HDIM];
__device__ __nv_bfloat16 g_vT2[(size_t)NB*NH*HDIM*2*SS];
__device__ __nv_bfloat16 g_attn2[(size_t)NB*NH*SS*2*SS];

__device__ __forceinline__ float gelu_exact(float v) {
    return 0.5f * v * (1.0f + erff(v * 0.70710678118654752440f));
}
__device__ __forceinline__ uint32_t smem_u32(const void* p) {
    uint32_t a;
    asm("{ .reg .u64 t; cvta.to.shared.u64 t, %1; cvt.u32.u64 %0, t; }" : "=r"(a) : "l"(p));
    return a;
}

#define LDSM4(r0,r1,r2,r3,addr) \
    asm volatile("ldmatrix.sync.aligned.m8n8.x4.shared.b16 {%0,%1,%2,%3}, [%4];" \
        : "=r"(r0), "=r"(r1), "=r"(r2), "=r"(r3) : "r"(addr))

#define MMA16816(d, a, b0, b1) \
    asm volatile("mma.sync.aligned.m16n8k16.row.col.f32.bf16.bf16.f32 " \
        "{%0,%1,%2,%3},{%4,%5,%6,%7},{%8,%9},{%0,%1,%2,%3};" \
        : "+f"((d)[0]), "+f"((d)[1]), "+f"((d)[2]), "+f"((d)[3]) \
        : "r"((a)[0]), "r"((a)[1]), "r"((a)[2]), "r"((a)[3]), "r"(b0), "r"(b1))

#define CP_ASYNC16(dst, src, sz) \
    asm volatile("cp.async.ca.shared.global [%0], [%1], 16, %2;" :: "r"(dst), "l"(src), "r"(sz))
#define CP_COMMIT() asm volatile("cp.async.commit_group;" ::: "memory")
#define CP_WAIT1() asm volatile("cp.async.wait_group 1;" ::: "memory")

// ================= mma.sync bf16 split GEMM (3-stage pipeline) =================
#define RSTRIDE 144
#define ATILE (128*RSTRIDE)        // 18432
#define BUFSZ (2*ATILE)            // 36864
#define STAGES 3
#define TG_SMEM (STAGES*BUFSZ)     // 110592

// OMODE: 0 = fp32 out (C); 1 = 3-way bf16 split out (C3, row stride ldc, segments at segoff)
template<int NP, int ACT, int OMODE>
__global__ void __launch_bounds__(256)
tgemm_k(const __nv_bfloat16* __restrict__ A, const __nv_bfloat16* __restrict__ B,
        const float* __restrict__ bias, float* __restrict__ C, __nv_bfloat16* __restrict__ C3,
        int M, int K, int lda, int ldb, int ldc, int segoff,
        long long sAi, long long sAo, long long sBi, long long sBo,
        long long sCi, long long sCo, long long sbias, int innerN)
{
    const int segA_[6] = {0,0,1,0,1,2};
    const int segB_[6] = {0,1,0,2,1,0};
    extern __shared__ char smem[];
    uint32_t sb = smem_u32(smem);
    int tid = threadIdx.x;
    int z = blockIdx.z, zi = z % innerN, zo = z / innerN;
    A += (size_t)(zi*sAi + zo*sAo);
    B += (size_t)(zi*sBi + zo*sBo);
    if (OMODE == 0) C  += (size_t)(zi*sCi + zo*sCo);
    else            C3 += (size_t)(zi*sCi + zo*sCo);
    int m0 = blockIdx.y * 128, n0 = blockIdx.x * 128;

    const int KPC = K >> 6;
    const int NC = NP * KPC;

    auto issue = [&](int kc, int buf) {
        int p = kc / KPC;
        int k0 = (kc - p * KPC) << 6;
        const __nv_bfloat16* Ap = A + (size_t)segA_[p] * K + k0;
        const __nv_bfloat16* Bp = B + (size_t)segB_[p] * K + k0;
        uint32_t sA = sb + buf * BUFSZ;
        uint32_t sB = sA + ATILE;
        #pragma unroll
        for (int i = 0; i < 4; i++) {
            int f = tid + (i << 8);
            int row = f >> 3, c = f & 7;
            int gr = m0 + row;
            int grc = gr < M ? gr : (M - 1);
            const void* src = Ap + (size_t)grc * lda + c * 8;
            uint32_t sz = gr < M ? 16u : 0u;
            CP_ASYNC16(sA + row * RSTRIDE + c * 16, src, sz);
        }
        #pragma unroll
        for (int i = 0; i < 4; i++) {
            int f = tid + (i << 8);
            int row = f >> 3, c = f & 7;
            const void* src = Bp + (size_t)(n0 + row) * ldb + c * 8;
            CP_ASYNC16(sB + row * RSTRIDE + c * 16, src, 16u);
        }
    };

    int lane = tid & 31, w = tid >> 5;
    int wm = w & 1, wn = w >> 1;
    uint32_t a_row = ((lane >> 3) & 1) * 8 + (lane & 7);
    uint32_t a_cs  = lane >> 4;
    uint32_t b_row = (lane >> 4) * 8 + (lane & 7);
    uint32_t b_cs  = (lane >> 3) & 1;

    float acc[4][4][4];
    #pragma unroll
    for (int i = 0; i < 4; i++)
        #pragma unroll
        for (int j = 0; j < 4; j++)
            #pragma unroll
            for (int r = 0; r < 4; r++) acc[i][j][r] = 0.f;

    issue(0, 0); CP_COMMIT();
    issue(1, 1); CP_COMMIT();

    for (int kc = 0; kc < NC; kc++) {
        CP_WAIT1();
        __syncthreads();
        // refill the buffer freed by last iteration's compute
        if (kc + 2 < NC) issue(kc + 2, (kc + 2) % STAGES);
        CP_COMMIT();   // unconditional: keeps wait_group accounting exact at the tail

        uint32_t sA = sb + (kc % STAGES) * BUFSZ;
        uint32_t sB = sA + ATILE;
        #pragma unroll
        for (int ks = 0; ks < 4; ks++) {
            uint32_t av[4][4], bv[2][4];
            #pragma unroll
            for (int mt = 0; mt < 4; mt++) {
                uint32_t ad = sA + (wm*64 + mt*16 + a_row) * RSTRIDE + ((ks*2 + a_cs) << 4);
                LDSM4(av[mt][0], av[mt][1], av[mt][2], av[mt][3], ad);
            }
            #pragma unroll
            for (int bt = 0; bt < 2; bt++) {
                uint32_t bd = sB + (wn*32 + bt*16 + b_row) * RSTRIDE + ((ks*2 + b_cs) << 4);
                LDSM4(bv[bt][0], bv[bt][1], bv[bt][2], bv[bt][3], bd);
            }
            #pragma unroll
            for (int mt = 0; mt < 4; mt++)
                #pragma unroll
                for (int nt = 0; nt < 4; nt++) {
                    uint32_t b0 = bv[nt >> 1][(nt & 1) * 2];
                    uint32_t b1 = bv[nt >> 1][(nt & 1) * 2 + 1];
                    MMA16816(acc[mt][nt], av[mt], b0, b1);
                }
        }
    }

    // ---- epilogue ----
    if (bias) bias += (size_t)z * (size_t)sbias;
    #pragma unroll
    for (int mt = 0; mt < 4; mt++) {
        int r0 = m0 + wm*64 + mt*16 + (lane >> 2);
        #pragma unroll
        for (int nt = 0; nt < 4; nt++) {
            int col = n0 + wn*32 + nt*8 + (lane & 3)*2;
            float bb0 = 0.f, bb1 = 0.f;
            if (bias) { bb0 = bias[col]; bb1 = bias[col+1]; }
            #pragma unroll
            for (int half = 0; half < 2; half++) {
                int r = r0 + half*8;
                if (r >= M) continue;
                float v0 = acc[mt][nt][half*2]   + bb0;
                float v1 = acc[mt][nt][half*2+1] + bb1;
                if (ACT == 1) { v0 = gelu_exact(v0); v1 = gelu_exact(v1); }
                if (OMODE == 0) {
                    *(float2*)(C + (size_t)r*ldc + col) = make_float2(v0, v1);
                } else {
                    __nv_bfloat16* d = C3 + (size_t)r*ldc + col;
                    __nv_bfloat16 h0 = __float2bfloat16_rn(v0);
                    __nv_bfloat16 h1 = __float2bfloat16_rn(v1);
                    float q0 = v0 - __bfloat162float(h0);
                    float q1 = v1 - __bfloat162float(h1);
                    __nv_bfloat16 m0b = __float2bfloat16_rn(q0);
                    __nv_bfloat16 m1b = __float2bfloat16_rn(q1);
                    __nv_bfloat16 l0 = __float2bfloat16_rn(q0 - __bfloat162float(m0b));
                    __nv_bfloat16 l1 = __float2bfloat16_rn(q1 - __bfloat162float(m1b));
                    *(__nv_bfloat162*)(d)            = __nv_bfloat162(h0, h1);
                    *(__nv_bfloat162*)(d + segoff)   = __nv_bfloat162(m0b, m1b);
                    *(__nv_bfloat162*)(d + 2*segoff) = __nv_bfloat162(l0, l1);
                }
            }
        }
    }
}

// ================= split kernels =================
__global__ void split3_k(const float* __restrict__ src, __nv_bfloat16* __restrict__ dst,
                         long long total, int C) {
    long long idx = (long long)blockIdx.x * 256 + threadIdx.x;
    if (idx >= total) return;
    long long r = idx / C; int c = (int)(idx % C);
    float v = src[idx];
    __nv_bfloat16 h = __float2bfloat16_rn(v);
    float r1 = v - __bfloat162float(h);
    __nv_bfloat16 m = __float2bfloat16_rn(r1);
    __nv_bfloat16 l = __float2bfloat16_rn(r1 - __bfloat162float(m));
    __nv_bfloat16* d = dst + r * (3LL*C) + c;
    d[0] = h; d[C] = m; d[2*C] = l;
}

__global__ void bi3_k() {
    long long idx = (long long)blockIdx.x * 256 + threadIdx.x;   // uint4 units
    const long long total = (long long)ROWS_DET * (3*2*DD) / 8;
    if (idx >= total) return;
    int row = (int)(idx / (3*2*DD/8));
    int k8  = (int)(idx % (3*2*DD/8)) * 8;
    int seg = k8 / (2*DD);
    int kk  = k8 % (2*DD);
    int b = row / SM1, s = row % SM1;
    int srow = s + (kk >= DD ? 1 : 0);
    int scol = seg*DD + (kk >= DD ? kk - DD : kk);
    const uint4* src = (const uint4*)(g_x3 + ((size_t)(b*SS + srow))*(3*DD) + scol);
    ((uint4*)g_bi3)[idx] = *src;
}

__global__ void split_qk_k() {
    long long idx = (long long)blockIdx.x * 256 + threadIdx.x;
    const long long total = (long long)NB*NH*SS*HDIM;
    if (idx >= total) return;
    int c = (int)(idx & 127);
    long long t = idx >> 7;
    int s = (int)(t & 1023);
    int z = (int)(t >> 10);
    int b = z / NH, h = z % NH;
    const float* base = g_qkv + ((size_t)(b*SS + s))*(3*DD) + h*HDIM + c;
    size_t o = ((size_t)z*SS + s) * (2*HDIM) + c;
    {
        float v = base[0];
        __nv_bfloat16 hi = __float2bfloat16_rn(v);
        g_q2[o] = hi; g_q2[o + HDIM] = __float2bfloat16_rn(v - __bfloat162float(hi));
    }
    {
        float v = base[DD];
        __nv_bfloat16 hi = __float2bfloat16_rn(v);
        g_k2[o] = hi; g_k2[o + HDIM] = __float2bfloat16_rn(v - __bfloat162float(hi));
    }
}

__global__ void split_vT_k() {
    long long idx = (long long)blockIdx.x * 256 + threadIdx.x;
    const long long total = (long long)NB*NH*HDIM*SS;
    if (idx >= total) return;
    int s = (int)(idx & 1023);
    long long t = idx >> 10;
    int c = (int)(t & 127);
    int z = (int)(t >> 7);
    int b = z / NH, h = z % NH;
    float v = g_qkv[((size_t)(b*SS + s))*(3*DD) + 2*DD + h*HDIM + c];
    __nv_bfloat16 hi = __float2bfloat16_rn(v);
    size_t o = ((size_t)z*HDIM + c) * (2*SS) + s;
    g_vT2[o] = hi;
    g_vT2[o + SS] = __float2bfloat16_rn(v - __bfloat162float(hi));
}

// ---------------- small kernels ----------------
__global__ void norm_k() {
    int r = blockIdx.x;
    const float* p = g_xling + (size_t)r * DD;
    float ss = 0.f;
    for (int i = threadIdx.x; i < DD; i += 256) { float v = p[i]; ss += v*v; }
    __shared__ float sh[256];
    sh[threadIdx.x] = ss; __syncthreads();
    for (int o = 128; o > 0; o >>= 1) {
        if (threadIdx.x < o) sh[threadIdx.x] += sh[threadIdx.x + o];
        __syncthreads();
    }
    if (threadIdx.x == 0) g_norm[r] = fmaxf(sqrtf(sh[0]), 1e-8f);
}

__global__ void cos_k() {
    int b = blockIdx.y, t = blockIdx.x;
    int scale, i;
    if (t < 1023)      { scale = 1; i = t; }
    else if (t < 1534) { scale = 2; i = t - 1023; }
    else               { scale = 4; i = t - 1534; }
    int s0 = i * scale, s1 = s0 + scale;
    const float* a = g_xling + ((size_t)b*SS + s0) * DD;
    const float* c = g_xling + ((size_t)b*SS + s1) * DD;
    float d = 0.f;
    for (int j = threadIdx.x; j < DD; j += 256) d += a[j] * c[j];
    __shared__ float sh[256];
    sh[threadIdx.x] = d; __syncthreads();
    for (int o = 128; o > 0; o >>= 1) {
        if (threadIdx.x < o) sh[threadIdx.x] += sh[threadIdx.x + o];
        __syncthreads();
    }
    if (threadIdx.x == 0)
        g_cs[b*CS_TOT + t] = sh[0] / (g_norm[b*SS + s0] * g_norm[b*SS + s1]);
}

__global__ void base_k() {
    int idx = blockIdx.x * 256 + threadIdx.x;
    if (idx >= NB*SM1) return;
    int b = idx / SM1, j = idx % SM1;
    const int Ls[3]   = {1023, 511, 255};
    const int offs[3] = {0, 1023, 1534};
    float acc = 0.f;
    #pragma unroll
    for (int u = 0; u < 3; u++) {
        int L = Ls[u];
        float ratio = (float)((double)L / 1023.0);
        float src = ((float)j + 0.5f) * ratio - 0.5f;
        src = fminf(fmaxf(src, 0.0f), (float)(L - 1));
        int i0 = (int)floorf(src);
        int i1 = min(i0 + 1, L - 1);
        float w = src - (float)i0;
        const float* cs = g_cs + b*CS_TOT + offs[u];
        acc += cs[i0] * (1.0f - w) + cs[i1] * w;
    }
    g_base[idx] = 0.5f * (1.0f - acc / 3.0f);
}

__global__ void learned_final_k(const float* __restrict__ detW3,
                                const float* __restrict__ detb3) {
    int r = blockIdx.x;
    __shared__ float sh[256];
    __shared__ float sacc;
    if (threadIdx.x == 0) sacc = 0.f;
    for (int n = 0; n < 3; n++) {
        const float* h2p = g_h2 + ((size_t)n*ROWS_DET + r) * (DD/2);
        const float* w   = detW3 + n*(DD/2);
        float part = 0.f;
        for (int j = threadIdx.x; j < DD/2; j += 256) part += h2p[j] * w[j];
        __syncthreads();
        sh[threadIdx.x] = part; __syncthreads();
        for (int o = 128; o > 0; o >>= 1) {
            if (threadIdx.x < o) sh[threadIdx.x] += sh[threadIdx.x + o];
            __syncthreads();
        }
        if (threadIdx.x == 0) {
            float t = sh[0] + detb3[n];
            sacc += 1.0f / (1.0f + expf(-t));
        }
        __syncthreads();
    }
    if (threadIdx.x == 0)
        g_final[r] = 0.6f * g_base[r] + 0.4f * (sacc / 3.0f);
}

__global__ void seg_k() {
    int b = threadIdx.x;
    if (b >= NB) return;
    int cum = 0;
    for (int s = 0; s < SS; s++) {
        float bv = (s == 0) ? 1.0f : g_final[b*SM1 + s - 1];
        cum += (bv > 0.5f) ? 1 : 0;
        g_seg[b*SS + s] = cum - 1;
    }
    for (int m = 0; m < MAXC; m++) { g_segcount[b*MAXC+m] = 0; g_segstart[b*MAXC+m] = 0; }
    for (int s = 0; s < SS; s++) {
        int m = g_seg[b*SS + s];
        if (m < MAXC) {
            if (g_segcount[b*MAXC+m] == 0) g_segstart[b*MAXC+m] = s;
            g_segcount[b*MAXC+m]++;
        }
    }
}

// softmax: reads fp32 scores once, writes 2-way bf16 split probs to g_attn2
__global__ void softmax_k() {
    int z = blockIdx.y, b = z / NH, q = blockIdx.x;
    const float* row = g_scores + (size_t)z*SS*SS + (size_t)q*SS;
    __nv_bfloat16* arow = g_attn2 + ((size_t)z*SS + q) * (2*SS);
    __shared__ float sv[SS];
    __shared__ int   sseg[SS];
    __shared__ float sh[256];
    int sq = g_seg[b*SS + q];
    const float scale = 0.088388347648318440550f;   // 1/sqrt(128)
    for (int k = threadIdx.x; k < SS; k += 256) {
        sseg[k] = g_seg[b*SS + k];
        sv[k] = row[k];
    }
    __syncthreads();
    float mx = -3.402823e38f;
    for (int k = threadIdx.x; k < SS; k += 256) {
        float v = (sseg[k] == sq) ? sv[k]*scale : -1e9f;
        mx = fmaxf(mx, v);
    }
    sh[threadIdx.x] = mx; __syncthreads();
    for (int o = 128; o > 0; o >>= 1) {
        if (threadIdx.x < o) sh[threadIdx.x] = fmaxf(sh[threadIdx.x], sh[threadIdx.x+o]);
        __syncthreads();
    }
    mx = sh[0]; __syncthreads();
    float sum = 0.f;
    for (int k = threadIdx.x; k < SS; k += 256) {
        float v = (sseg[k] == sq) ? sv[k]*scale : -1e9f;
        float e = expf(v - mx);
        sv[k] = e;
        sum += e;
    }
    sh[threadIdx.x] = sum; __syncthreads();
    for (int o = 128; o > 0; o >>= 1) {
        if (threadIdx.x < o) sh[threadIdx.x] += sh[threadIdx.x+o];
        __syncthreads();
    }
    float inv = 1.0f / sh[0];
    __syncthreads();
    for (int k = threadIdx.x; k < SS; k += 256) {
        float pv = sv[k] * inv;
        __nv_bfloat16 hi = __float2bfloat16_rn(pv);
        arow[k]      = hi;
        arow[SS + k] = __float2bfloat16_rn(pv - __bfloat162float(hi));
    }
}

// pooling + embeddings, writes 3-way split chunk directly
__global__ void chunk_k(const float* __restrict__ size_emb,
                        const float* __restrict__ pos_enc) {
    int m = blockIdx.x, b = blockIdx.y;
    int cnt = g_segcount[b*MAXC + m];
    int st  = g_segstart[b*MAXC + m];
    __nv_bfloat16* drow = g_chunk3 + ((size_t)b*MAXC + m) * (3*DD);
    for (int d = threadIdx.x; d < DD; d += 256) {
        float v;
        if (cnt > 0) {
            float sum = 0.f;
            for (int s = st; s < st + cnt; s++)
                sum += g_attnout[((size_t)b*SS + s)*DD + d];
            int cl = min(cnt, 1023);
            v = sum / (float)cnt + size_emb[(size_t)cl*DD + d];
        } else v = 0.f;
        v += pos_enc[(size_t)m*DD + d];
        __nv_bfloat16 h = __float2bfloat16_rn(v);
        float r1 = v - __bfloat162float(h);
        __nv_bfloat16 mm = __float2bfloat16_rn(r1);
        drow[d]        = h;
        drow[DD + d]   = mm;
        drow[2*DD + d] = __float2bfloat16_rn(r1 - __bfloat162float(mm));
    }
}

__global__ void ln_k(const float* __restrict__ gamma,
                     const float* __restrict__ beta,
                     float* __restrict__ out) {
    int r = blockIdx.x;
    const float* y = g_y + (size_t)r*DD;
    __shared__ float sh[256];
    float s = 0.f;
    for (int d = threadIdx.x; d < DD; d += 256) s += y[d];
    sh[threadIdx.x] = s; __syncthreads();
    for (int o = 128; o > 0; o >>= 1) {
        if (threadIdx.x < o) sh[threadIdx.x] += sh[threadIdx.x+o];
        __syncthreads();
    }
    float mu = sh[0] / (float)DD; __syncthreads();
    float v2 = 0.f;
    for (int d = threadIdx.x; d < DD; d += 256) { float t = y[d]-mu; v2 += t*t; }
    sh[threadIdx.x] = v2; __syncthreads();
    for (int o = 128; o > 0; o >>= 1) {
        if (threadIdx.x < o) sh[threadIdx.x] += sh[threadIdx.x+o];
        __syncthreads();
    }
    float inv = 1.0f / sqrtf(sh[0] / (float)DD + 1e-5f);
    for (int d = threadIdx.x; d < DD; d += 256)
        out[(size_t)r*DD + d] = (y[d] - mu) * inv * gamma[d] + beta[d];
}

// ---------------- host launchers ----------------
struct GemmArgs {
    const __nv_bfloat16 *A, *B;
    const float* bias;
    float* C;
    __nv_bfloat16* C3;
    int M, N, K, lda, ldb, ldc, segoff;
    long long sAi, sAo, sBi, sBo, sCi, sCo, sbias;
    int innerN, batch;
};

template<int NP, int ACT, int OMODE>
static void tg_launch(const GemmArgs& a) {
    dim3 grid(a.N/128, (a.M + 127)/128, a.batch);
    tgemm_k<NP,ACT,OMODE><<<grid,256,TG_SMEM>>>(a.A, a.B, a.bias, a.C, a.C3,
        a.M, a.K, a.lda, a.ldb, a.ldc, a.segoff,
        a.sAi, a.sAo, a.sBi, a.sBo, a.sCi, a.sCo, a.sbias, a.innerN);
}

static void split3(const float* src, __nv_bfloat16* dst, long long rows, int cols) {
    long long total = rows * cols;
    split3_k<<<(unsigned)((total + 255)/256), 256>>>(src, dst, total, cols);
}

extern "C" void kernel_launch(void* const* d_in, const int* in_sizes, int n_in,
                              void* d_out, int out_size) {
    const float* x         = (const float*)d_in[0];
    const float* Wp        = (const float*)d_in[1];
    const float* bp        = (const float*)d_in[2];
    const float* detW1     = (const float*)d_in[3];
    const float* detb1     = (const float*)d_in[4];
    const float* detW2     = (const float*)d_in[5];
    const float* detb2     = (const float*)d_in[6];
    const float* detW3     = (const float*)d_in[7];
    const float* detb3     = (const float*)d_in[8];
    const float* in_proj_w = (const float*)d_in[9];
    const float* in_proj_b = (const float*)d_in[10];
    const float* out_w     = (const float*)d_in[11];
    const float* out_b     = (const float*)d_in[12];
    const float* size_emb  = (const float*)d_in[13];
    const float* pos_enc   = (const float*)d_in[14];
    const float* procW1    = (const float*)d_in[15];
    const float* procb1    = (const float*)d_in[16];
    const float* procW2    = (const float*)d_in[17];
    const float* procb2    = (const float*)d_in[18];
    const float* ln_g      = (const float*)d_in[19];
    const float* ln_b      = (const float*)d_in[20];
    float* outp = (float*)d_out;

    cudaFuncSetAttribute(tgemm_k<6,0,0>, cudaFuncAttributeMaxDynamicSharedMemorySize, TG_SMEM);
    cudaFuncSetAttribute(tgemm_k<6,1,0>, cudaFuncAttributeMaxDynamicSharedMemorySize, TG_SMEM);
    cudaFuncSetAttribute(tgemm_k<6,1,1>, cudaFuncAttributeMaxDynamicSharedMemorySize, TG_SMEM);
    cudaFuncSetAttribute(tgemm_k<3,0,0>, cudaFuncAttributeMaxDynamicSharedMemorySize, TG_SMEM);
    cudaFuncSetAttribute(tgemm_k<3,0,1>, cudaFuncAttributeMaxDynamicSharedMemorySize, TG_SMEM);
    cudaFuncSetAttribute(tgemm_k<3,1,1>, cudaFuncAttributeMaxDynamicSharedMemorySize, TG_SMEM);

    void *p;
    cudaGetSymbolAddress(&p, g_xling);   float* xling   = (float*)p;
    cudaGetSymbolAddress(&p, g_h2);      float* h2      = (float*)p;
    cudaGetSymbolAddress(&p, g_qkv);     float* qkv     = (float*)p;
    cudaGetSymbolAddress(&p, g_scores);  float* scores  = (float*)p;
    cudaGetSymbolAddress(&p, g_attnout); float* attnout = (float*)p;
    cudaGetSymbolAddress(&p, g_y);       float* yb      = (float*)p;
    cudaGetSymbolAddress(&p, g_x3);      __nv_bfloat16* x3      = (__nv_bfloat16*)p;
    cudaGetSymbolAddress(&p, g_Wp3);     __nv_bfloat16* Wp3     = (__nv_bfloat16*)p;
    cudaGetSymbolAddress(&p, g_bi3);     __nv_bfloat16* bi3     = (__nv_bfloat16*)p;
    cudaGetSymbolAddress(&p, g_detW1_3); __nv_bfloat16* dW1_3   = (__nv_bfloat16*)p;
    cudaGetSymbolAddress(&p, g_h1_3);    __nv_bfloat16* h1_3    = (__nv_bfloat16*)p;
    cudaGetSymbolAddress(&p, g_detW2_3); __nv_bfloat16* dW2_3   = (__nv_bfloat16*)p;
    cudaGetSymbolAddress(&p, g_wqkv3);   __nv_bfloat16* wqkv3   = (__nv_bfloat16*)p;
    cudaGetSymbolAddress(&p, g_ctx3);    __nv_bfloat16* ctx3    = (__nv_bfloat16*)p;
    cudaGetSymbolAddress(&p, g_outw3);   __nv_bfloat16* outw3   = (__nv_bfloat16*)p;
    cudaGetSymbolAddress(&p, g_chunk3);  __nv_bfloat16* chunk3  = (__nv_bfloat16*)p;
    cudaGetSymbolAddress(&p, g_pw1_3);   __nv_bfloat16* pw1_3   = (__nv_bfloat16*)p;
    cudaGetSymbolAddress(&p, g_hproc3);  __nv_bfloat16* hproc3  = (__nv_bfloat16*)p;
    cudaGetSymbolAddress(&p, g_pw2_3);   __nv_bfloat16* pw2_3   = (__nv_bfloat16*)p;
    cudaGetSymbolAddress(&p, g_q2);      __nv_bfloat16* q2      = (__nv_bfloat16*)p;
    cudaGetSymbolAddress(&p, g_k2);      __nv_bfloat16* k2      = (__nv_bfloat16*)p;
    cudaGetSymbolAddress(&p, g_vT2);     __nv_bfloat16* vT2     = (__nv_bfloat16*)p;
    cudaGetSymbolAddress(&p, g_attn2);   __nv_bfloat16* attn2   = (__nv_bfloat16*)p;

    // ===== input splits =====
    split3(x, x3, NB*SS, DD);
    split3(Wp, Wp3, DD, DD);
    split3(detW1, dW1_3, 3*DD, 2*DD);
    split3(detW2, dW2_3, 3*(DD/2), DD);
    split3(in_proj_w, wqkv3, 3*DD, DD);
    split3(out_w, outw3, DD, DD);
    split3(procW1, pw1_3, 2*DD, DD);
    split3(procW2, pw2_3, DD, 2*DD);
    {
        long long total8 = (long long)ROWS_DET * (3*2*DD) / 8;
        bi3_k<<<(unsigned)((total8 + 255)/256), 256>>>();
    }

    // ===== boundary path (6-product) =====
    { GemmArgs a = { x3, Wp3, bp, xling, nullptr, NB*SS, DD, DD, 3*DD, 3*DD, DD, 0,
                     0,0,0,0,0,0,0, 1, 1 };
      tg_launch<6,0,0>(a); }
    norm_k<<<NB*SS, 256>>>();
    cos_k<<<dim3(CS_TOT, NB), 256>>>();
    base_k<<<(NB*SM1 + 255)/256, 256>>>();
    // h1 = gelu(bi @ detW1[n]^T + b) -> 3-way split directly
    { GemmArgs a = { bi3, dW1_3, detb1, nullptr, h1_3, ROWS_DET, DD, 2*DD,
                     3*2*DD, 3*2*DD, 3*DD, DD,
                     0, 0, (long long)DD*3*2*DD, 0,
                     (long long)ROWS_DET*3*DD, 0, DD, 3, 3 };
      tg_launch<6,1,1>(a); }
    // h2 = gelu(h1 @ detW2[n]^T + b) fp32
    { GemmArgs a = { h1_3, dW2_3, detb2, h2, nullptr, ROWS_DET, DD/2, DD,
                     3*DD, 3*DD, DD/2, 0,
                     (long long)ROWS_DET*3*DD, 0, (long long)(DD/2)*3*DD, 0,
                     (long long)ROWS_DET*(DD/2), 0, DD/2, 3, 3 };
      tg_launch<6,1,0>(a); }
    learned_final_k<<<ROWS_DET, 256>>>(detW3, detb3);
    seg_k<<<1, NB>>>();

    // ===== continuous path (3-product) =====
    { GemmArgs a = { x3, wqkv3, in_proj_b, qkv, nullptr, NB*SS, 3*DD, DD,
                     3*DD, 3*DD, 3*DD, 0, 0,0,0,0,0,0,0, 1, 1 };
      tg_launch<3,0,0>(a); }
    {
        long long t = (long long)NB*NH*SS*HDIM;
        split_qk_k<<<(unsigned)((t+255)/256), 256>>>();
        split_vT_k<<<(unsigned)((t+255)/256), 256>>>();
    }
    // scores[z] = q_z @ k_z^T
    { GemmArgs a = { q2, k2, nullptr, scores, nullptr, SS, SS, HDIM,
                     2*HDIM, 2*HDIM, SS, 0,
                     (long long)SS*2*HDIM, (long long)NH*SS*2*HDIM,
                     (long long)SS*2*HDIM, (long long)NH*SS*2*HDIM,
                     (long long)SS*SS, (long long)NH*SS*SS, 0, NH, NB*NH };
      tg_launch<3,0,0>(a); }
    softmax_k<<<dim3(SS, NB*NH), 256>>>();
    // ctx[z] = attn_z @ v_z -> 3-way split directly (layout [b,s][3*DD], inner offset h*HDIM)
    { GemmArgs a = { attn2, vT2, nullptr, nullptr, ctx3, SS, HDIM, SS,
                     2*SS, 2*SS, 3*DD, DD,
                     (long long)SS*2*SS, (long long)NH*SS*2*SS,
                     (long long)HDIM*2*SS, (long long)NH*HDIM*2*SS,
                     (long long)HDIM, (long long)SS*3*DD, 0, NH, NB*NH };
      tg_launch<3,0,1>(a); }
    // attn_out = ctx @ out_w^T + out_b
    { GemmArgs a = { ctx3, outw3, out_b, attnout, nullptr, NB*SS, DD, DD,
                     3*DD, 3*DD, DD, 0, 0,0,0,0,0,0,0, 1, 1 };
      tg_launch<3,0,0>(a); }
    chunk_k<<<dim3(MAXC, NB), 256>>>(size_emb, pos_enc);
    // hproc = gelu(chunk @ procW1^T + b) -> 3-way split directly
    { GemmArgs a = { chunk3, pw1_3, procb1, nullptr, hproc3, NB*MAXC, 2*DD, DD,
                     3*DD, 3*DD, 3*2*DD, 2*DD, 0,0,0,0,0,0,0, 1, 1 };
      tg_launch<3,1,1>(a); }
    // y = hproc @ procW2^T + b
    { GemmArgs a = { hproc3, pw2_3, procb2, yb, nullptr, NB*MAXC, DD, 2*DD,
                     3*2*DD, 3*2*DD, DD, 0, 0,0,0,0,0,0,0, 1, 1 };
      tg_launch<3,0,0>(a); }
    ln_k<<<NB*MAXC, 256>>>(ln_g, ln_b, outp);
}

// round 5
// speedup vs baseline: 1.1247x; 1.1247x over previous
#include <cuda_runtime.h>
#include <cuda_bf16.h>
#include <math.h>
#include <stdint.h>

// ---------------- problem constants ----------------
#define NB 4
#define SS 1024
#define DD 1536
#define NH 12
#define HDIM 128
#define MAXC 256
#define SM1 1023
#define ROWS_DET (NB*SM1)        // 4092
#define CS_TOT (1023+511+255)    // 1789

// ---------------- fp32 scratch ----------------
__device__ float g_xling[(size_t)NB*SS*DD];
__device__ float g_norm[NB*SS];
__device__ float g_cs[NB*CS_TOT];
__device__ float g_base[NB*SM1];
__device__ float g_h2[(size_t)3*ROWS_DET*(DD/2)];
__device__ float g_final[NB*SM1];
__device__ int   g_seg[NB*SS];
__device__ int   g_segstart[NB*MAXC];
__device__ int   g_segcount[NB*MAXC];
__device__ float g_qkv[(size_t)NB*SS*3*DD];
__device__ float g_scores[(size_t)NB*NH*SS*SS];
__device__ float g_attnout[(size_t)NB*SS*DD];
__device__ float g_y[(size_t)NB*MAXC*DD];

// ---------------- bf16 split scratch ----------------
__device__ __nv_bfloat16 g_x3[(size_t)NB*SS*3*DD];
__device__ __nv_bfloat16 g_Wp3[(size_t)DD*3*DD];
__device__ __nv_bfloat16 g_bi3[(size_t)ROWS_DET*3*(2*DD)];
__device__ __nv_bfloat16 g_detW1_3[(size_t)3*DD*3*(2*DD)];
__device__ __nv_bfloat16 g_h1_3[(size_t)3*ROWS_DET*3*DD];
__device__ __nv_bfloat16 g_detW2_3[(size_t)3*(DD/2)*3*DD];
__device__ __nv_bfloat16 g_wqkv3[(size_t)3*DD*3*DD];
__device__ __nv_bfloat16 g_ctx3[(size_t)NB*SS*3*DD];
__device__ __nv_bfloat16 g_outw3[(size_t)DD*3*DD];
__device__ __nv_bfloat16 g_chunk3[(size_t)NB*MAXC*3*DD];
__device__ __nv_bfloat16 g_pw1_3[(size_t)2*DD*3*DD];
__device__ __nv_bfloat16 g_hproc3[(size_t)NB*MAXC*3*2*DD];
__device__ __nv_bfloat16 g_pw2_3[(size_t)DD*3*2*DD];
__device__ __nv_bfloat16 g_q2[(size_t)NB*NH*SS*2*HDIM];
__device__ __nv_bfloat16 g_k2[(size_t)NB*NH*SS*2*HDIM];
__device__ __nv_bfloat16 g_vT2[(size_t)NB*NH*HDIM*2*SS];
__device__ __nv_bfloat16 g_attn2[(size_t)NB*NH*SS*2*SS];

__device__ __forceinline__ float gelu_exact(float v) {
    return 0.5f * v * (1.0f + erff(v * 0.70710678118654752440f));
}
__device__ __forceinline__ uint32_t smem_u32(const void* p) {
    uint32_t a;
    asm("{ .reg .u64 t; cvta.to.shared.u64 t, %1; cvt.u32.u64 %0, t; }" : "=r"(a) : "l"(p));
    return a;
}

#define LDSM4(r0,r1,r2,r3,addr) \
    asm volatile("ldmatrix.sync.aligned.m8n8.x4.shared.b16 {%0,%1,%2,%3}, [%4];" \
        : "=r"(r0), "=r"(r1), "=r"(r2), "=r"(r3) : "r"(addr))

#define MMA16816(d, a, b0, b1) \
    asm volatile("mma.sync.aligned.m16n8k16.row.col.f32.bf16.bf16.f32 " \
        "{%0,%1,%2,%3},{%4,%5,%6,%7},{%8,%9},{%0,%1,%2,%3};" \
        : "+f"((d)[0]), "+f"((d)[1]), "+f"((d)[2]), "+f"((d)[3]) \
        : "r"((a)[0]), "r"((a)[1]), "r"((a)[2]), "r"((a)[3]), "r"(b0), "r"(b1))

#define CP_ASYNC16(dst, src, sz) \
    asm volatile("cp.async.ca.shared.global [%0], [%1], 16, %2;" :: "r"(dst), "l"(src), "r"(sz))
#define CP_COMMIT() asm volatile("cp.async.commit_group;" ::: "memory")
#define CP_WAIT1() asm volatile("cp.async.wait_group 1;" ::: "memory")
#define CP_WAIT0() asm volatile("cp.async.wait_group 0;" ::: "memory")

// ================= mma.sync bf16 split GEMM (2-stage, 2 CTAs/SM) =================
#define RSTRIDE 144
#define ATILE (128*RSTRIDE)        // 18432
#define BUFSZ (2*ATILE)            // 36864
#define TG_SMEM (2*BUFSZ)          // 73728 -> 2 CTAs/SM

// OMODE: 0 = fp32 out (C); 1 = 3-way bf16 split out (C3, row stride ldc, segments at segoff)
template<int NP, int ACT, int OMODE>
__global__ void __launch_bounds__(256)
tgemm_k(const __nv_bfloat16* __restrict__ A, const __nv_bfloat16* __restrict__ B,
        const float* __restrict__ bias, float* __restrict__ C, __nv_bfloat16* __restrict__ C3,
        int M, int K, int lda, int ldb, int ldc, int segoff,
        long long sAi, long long sAo, long long sBi, long long sBo,
        long long sCi, long long sCo, long long sbias, int innerN)
{
    const int segA_[6] = {0,0,1,0,1,2};
    const int segB_[6] = {0,1,0,2,1,0};
    extern __shared__ char smem[];
    uint32_t sb = smem_u32(smem);
    int tid = threadIdx.x;
    int z = blockIdx.z, zi = z % innerN, zo = z / innerN;
    A += (size_t)(zi*sAi + zo*sAo);
    B += (size_t)(zi*sBi + zo*sBo);
    if (OMODE == 0) C  += (size_t)(zi*sCi + zo*sCo);
    else            C3 += (size_t)(zi*sCi + zo*sCo);
    int m0 = blockIdx.y * 128, n0 = blockIdx.x * 128;

    const int KPC = K >> 6;
    const int NC = NP * KPC;

    auto issue = [&](int kc, int buf) {
        int p = kc / KPC;
        int k0 = (kc - p * KPC) << 6;
        const __nv_bfloat16* Ap = A + (size_t)segA_[p] * K + k0;
        const __nv_bfloat16* Bp = B + (size_t)segB_[p] * K + k0;
        uint32_t sA = sb + buf * BUFSZ;
        uint32_t sB = sA + ATILE;
        #pragma unroll
        for (int i = 0; i < 4; i++) {
            int f = tid + (i << 8);
            int row = f >> 3, c = f & 7;
            int gr = m0 + row;
            int grc = gr < M ? gr : (M - 1);
            const void* src = Ap + (size_t)grc * lda + c * 8;
            uint32_t sz = gr < M ? 16u : 0u;
            CP_ASYNC16(sA + row * RSTRIDE + c * 16, src, sz);
        }
        #pragma unroll
        for (int i = 0; i < 4; i++) {
            int f = tid + (i << 8);
            int row = f >> 3, c = f & 7;
            const void* src = Bp + (size_t)(n0 + row) * ldb + c * 8;
            CP_ASYNC16(sB + row * RSTRIDE + c * 16, src, 16u);
        }
    };

    int lane = tid & 31, w = tid >> 5;
    int wm = w & 1, wn = w >> 1;
    uint32_t a_row = ((lane >> 3) & 1) * 8 + (lane & 7);
    uint32_t a_cs  = lane >> 4;
    uint32_t b_row = (lane >> 4) * 8 + (lane & 7);
    uint32_t b_cs  = (lane >> 3) & 1;

    float acc[4][4][4];
    #pragma unroll
    for (int i = 0; i < 4; i++)
        #pragma unroll
        for (int j = 0; j < 4; j++)
            #pragma unroll
            for (int r = 0; r < 4; r++) acc[i][j][r] = 0.f;

    issue(0, 0);
    CP_COMMIT();

    for (int kc = 0; kc < NC; kc++) {
        int cur = kc & 1;
        if (kc + 1 < NC) { issue(kc + 1, cur ^ 1); CP_COMMIT(); CP_WAIT1(); }
        else             { CP_WAIT0(); }
        __syncthreads();

        uint32_t sA = sb + cur * BUFSZ;
        uint32_t sB = sA + ATILE;
        #pragma unroll
        for (int ks = 0; ks < 4; ks++) {
            uint32_t av[4][4], bv[2][4];
            #pragma unroll
            for (int mt = 0; mt < 4; mt++) {
                uint32_t ad = sA + (wm*64 + mt*16 + a_row) * RSTRIDE + ((ks*2 + a_cs) << 4);
                LDSM4(av[mt][0], av[mt][1], av[mt][2], av[mt][3], ad);
            }
            #pragma unroll
            for (int bt = 0; bt < 2; bt++) {
                uint32_t bd = sB + (wn*32 + bt*16 + b_row) * RSTRIDE + ((ks*2 + b_cs) << 4);
                LDSM4(bv[bt][0], bv[bt][1], bv[bt][2], bv[bt][3], bd);
            }
            #pragma unroll
            for (int mt = 0; mt < 4; mt++)
                #pragma unroll
                for (int nt = 0; nt < 4; nt++) {
                    uint32_t b0 = bv[nt >> 1][(nt & 1) * 2];
                    uint32_t b1 = bv[nt >> 1][(nt & 1) * 2 + 1];
                    MMA16816(acc[mt][nt], av[mt], b0, b1);
                }
        }
        __syncthreads();
    }

    // ---- epilogue ----
    if (bias) bias += (size_t)z * (size_t)sbias;
    #pragma unroll
    for (int mt = 0; mt < 4; mt++) {
        int r0 = m0 + wm*64 + mt*16 + (lane >> 2);
        #pragma unroll
        for (int nt = 0; nt < 4; nt++) {
            int col = n0 + wn*32 + nt*8 + (lane & 3)*2;
            float bb0 = 0.f, bb1 = 0.f;
            if (bias) { bb0 = bias[col]; bb1 = bias[col+1]; }
            #pragma unroll
            for (int half = 0; half < 2; half++) {
                int r = r0 + half*8;
                if (r >= M) continue;
                float v0 = acc[mt][nt][half*2]   + bb0;
                float v1 = acc[mt][nt][half*2+1] + bb1;
                if (ACT == 1) { v0 = gelu_exact(v0); v1 = gelu_exact(v1); }
                if (OMODE == 0) {
                    *(float2*)(C + (size_t)r*ldc + col) = make_float2(v0, v1);
                } else {
                    __nv_bfloat16* d = C3 + (size_t)r*ldc + col;
                    __nv_bfloat16 h0 = __float2bfloat16_rn(v0);
                    __nv_bfloat16 h1 = __float2bfloat16_rn(v1);
                    float q0 = v0 - __bfloat162float(h0);
                    float q1 = v1 - __bfloat162float(h1);
                    __nv_bfloat16 m0b = __float2bfloat16_rn(q0);
                    __nv_bfloat16 m1b = __float2bfloat16_rn(q1);
                    __nv_bfloat16 l0 = __float2bfloat16_rn(q0 - __bfloat162float(m0b));
                    __nv_bfloat16 l1 = __float2bfloat16_rn(q1 - __bfloat162float(m1b));
                    *(__nv_bfloat162*)(d)            = __nv_bfloat162(h0, h1);
                    *(__nv_bfloat162*)(d + segoff)   = __nv_bfloat162(m0b, m1b);
                    *(__nv_bfloat162*)(d + 2*segoff) = __nv_bfloat162(l0, l1);
                }
            }
        }
    }
}

// ================= split kernels =================
__global__ void split3_k(const float* __restrict__ src, __nv_bfloat16* __restrict__ dst,
                         long long total, int C) {
    long long idx = (long long)blockIdx.x * 256 + threadIdx.x;
    if (idx >= total) return;
    long long r = idx / C; int c = (int)(idx % C);
    float v = src[idx];
    __nv_bfloat16 h = __float2bfloat16_rn(v);
    float r1 = v - __bfloat162float(h);
    __nv_bfloat16 m = __float2bfloat16_rn(r1);
    __nv_bfloat16 l = __float2bfloat16_rn(r1 - __bfloat162float(m));
    __nv_bfloat16* d = dst + r * (3LL*C) + c;
    d[0] = h; d[C] = m; d[2*C] = l;
}

__global__ void bi3_k() {
    long long idx = (long long)blockIdx.x * 256 + threadIdx.x;   // uint4 units
    const long long total = (long long)ROWS_DET * (3*2*DD) / 8;
    if (idx >= total) return;
    int row = (int)(idx / (3*2*DD/8));
    int k8  = (int)(idx % (3*2*DD/8)) * 8;
    int seg = k8 / (2*DD);
    int kk  = k8 % (2*DD);
    int b = row / SM1, s = row % SM1;
    int srow = s + (kk >= DD ? 1 : 0);
    int scol = seg*DD + (kk >= DD ? kk - DD : kk);
    const uint4* src = (const uint4*)(g_x3 + ((size_t)(b*SS + srow))*(3*DD) + scol);
    ((uint4*)g_bi3)[idx] = *src;
}

__global__ void split_qk_k() {
    long long idx = (long long)blockIdx.x * 256 + threadIdx.x;
    const long long total = (long long)NB*NH*SS*HDIM;
    if (idx >= total) return;
    int c = (int)(idx & 127);
    long long t = idx >> 7;
    int s = (int)(t & 1023);
    int z = (int)(t >> 10);
    int b = z / NH, h = z % NH;
    const float* base = g_qkv + ((size_t)(b*SS + s))*(3*DD) + h*HDIM + c;
    size_t o = ((size_t)z*SS + s) * (2*HDIM) + c;
    {
        float v = base[0];
        __nv_bfloat16 hi = __float2bfloat16_rn(v);
        g_q2[o] = hi; g_q2[o + HDIM] = __float2bfloat16_rn(v - __bfloat162float(hi));
    }
    {
        float v = base[DD];
        __nv_bfloat16 hi = __float2bfloat16_rn(v);
        g_k2[o] = hi; g_k2[o + HDIM] = __float2bfloat16_rn(v - __bfloat162float(hi));
    }
}

__global__ void split_vT_k() {
    long long idx = (long long)blockIdx.x * 256 + threadIdx.x;
    const long long total = (long long)NB*NH*HDIM*SS;
    if (idx >= total) return;
    int s = (int)(idx & 1023);
    long long t = idx >> 10;
    int c = (int)(t & 127);
    int z = (int)(t >> 7);
    int b = z / NH, h = z % NH;
    float v = g_qkv[((size_t)(b*SS + s))*(3*DD) + 2*DD + h*HDIM + c];
    __nv_bfloat16 hi = __float2bfloat16_rn(v);
    size_t o = ((size_t)z*HDIM + c) * (2*SS) + s;
    g_vT2[o] = hi;
    g_vT2[o + SS] = __float2bfloat16_rn(v - __bfloat162float(hi));
}

// ---------------- small kernels ----------------
__global__ void norm_k() {
    int r = blockIdx.x;
    const float* p = g_xling + (size_t)r * DD;
    float ss = 0.f;
    for (int i = threadIdx.x; i < DD; i += 256) { float v = p[i]; ss += v*v; }
    __shared__ float sh[256];
    sh[threadIdx.x] = ss; __syncthreads();
    for (int o = 128; o > 0; o >>= 1) {
        if (threadIdx.x < o) sh[threadIdx.x] += sh[threadIdx.x + o];
        __syncthreads();
    }
    if (threadIdx.x == 0) g_norm[r] = fmaxf(sqrtf(sh[0]), 1e-8f);
}

__global__ void cos_k() {
    int b = blockIdx.y, t = blockIdx.x;
    int scale, i;
    if (t < 1023)      { scale = 1; i = t; }
    else if (t < 1534) { scale = 2; i = t - 1023; }
    else               { scale = 4; i = t - 1534; }
    int s0 = i * scale, s1 = s0 + scale;
    const float* a = g_xling + ((size_t)b*SS + s0) * DD;
    const float* c = g_xling + ((size_t)b*SS + s1) * DD;
    float d = 0.f;
    for (int j = threadIdx.x; j < DD; j += 256) d += a[j] * c[j];
    __shared__ float sh[256];
    sh[threadIdx.x] = d; __syncthreads();
    for (int o = 128; o > 0; o >>= 1) {
        if (threadIdx.x < o) sh[threadIdx.x] += sh[threadIdx.x + o];
        __syncthreads();
    }
    if (threadIdx.x == 0)
        g_cs[b*CS_TOT + t] = sh[0] / (g_norm[b*SS + s0] * g_norm[b*SS + s1]);
}

__global__ void base_k() {
    int idx = blockIdx.x * 256 + threadIdx.x;
    if (idx >= NB*SM1) return;
    int b = idx / SM1, j = idx % SM1;
    const int Ls[3]   = {1023, 511, 255};
    const int offs[3] = {0, 1023, 1534};
    float acc = 0.f;
    #pragma unroll
    for (int u = 0; u < 3; u++) {
        int L = Ls[u];
        float ratio = (float)((double)L / 1023.0);
        float src = ((float)j + 0.5f) * ratio - 0.5f;
        src = fminf(fmaxf(src, 0.0f), (float)(L - 1));
        int i0 = (int)floorf(src);
        int i1 = min(i0 + 1, L - 1);
        float w = src - (float)i0;
        const float* cs = g_cs + b*CS_TOT + offs[u];
        acc += cs[i0] * (1.0f - w) + cs[i1] * w;
    }
    g_base[idx] = 0.5f * (1.0f - acc / 3.0f);
}

__global__ void learned_final_k(const float* __restrict__ detW3,
                                const float* __restrict__ detb3) {
    int r = blockIdx.x;
    __shared__ float sh[256];
    __shared__ float sacc;
    if (threadIdx.x == 0) sacc = 0.f;
    for (int n = 0; n < 3; n++) {
        const float* h2p = g_h2 + ((size_t)n*ROWS_DET + r) * (DD/2);
        const float* w   = detW3 + n*(DD/2);
        float part = 0.f;
        for (int j = threadIdx.x; j < DD/2; j += 256) part += h2p[j] * w[j];
        __syncthreads();
        sh[threadIdx.x] = part; __syncthreads();
        for (int o = 128; o > 0; o >>= 1) {
            if (threadIdx.x < o) sh[threadIdx.x] += sh[threadIdx.x + o];
            __syncthreads();
        }
        if (threadIdx.x == 0) {
            float t = sh[0] + detb3[n];
            sacc += 1.0f / (1.0f + expf(-t));
        }
        __syncthreads();
    }
    if (threadIdx.x == 0)
        g_final[r] = 0.6f * g_base[r] + 0.4f * (sacc / 3.0f);
}

__global__ void seg_k() {
    int b = threadIdx.x;
    if (b >= NB) return;
    int cum = 0;
    for (int s = 0; s < SS; s++) {
        float bv = (s == 0) ? 1.0f : g_final[b*SM1 + s - 1];
        cum += (bv > 0.5f) ? 1 : 0;
        g_seg[b*SS + s] = cum - 1;
    }
    for (int m = 0; m < MAXC; m++) { g_segcount[b*MAXC+m] = 0; g_segstart[b*MAXC+m] = 0; }
    for (int s = 0; s < SS; s++) {
        int m = g_seg[b*SS + s];
        if (m < MAXC) {
            if (g_segcount[b*MAXC+m] == 0) g_segstart[b*MAXC+m] = s;
            g_segcount[b*MAXC+m]++;
        }
    }
}

// softmax: reads fp32 scores once, writes 2-way bf16 split probs to g_attn2
__global__ void softmax_k() {
    int z = blockIdx.y, b = z / NH, q = blockIdx.x;
    const float* row = g_scores + (size_t)z*SS*SS + (size_t)q*SS;
    __nv_bfloat16* arow = g_attn2 + ((size_t)z*SS + q) * (2*SS);
    __shared__ float sv[SS];
    __shared__ int   sseg[SS];
    __shared__ float sh[256];
    int sq = g_seg[b*SS + q];
    const float scale = 0.088388347648318440550f;   // 1/sqrt(128)
    for (int k = threadIdx.x; k < SS; k += 256) {
        sseg[k] = g_seg[b*SS + k];
        sv[k] = row[k];
    }
    __syncthreads();
    float mx = -3.402823e38f;
    for (int k = threadIdx.x; k < SS; k += 256) {
        float v = (sseg[k] == sq) ? sv[k]*scale : -1e9f;
        mx = fmaxf(mx, v);
    }
    sh[threadIdx.x] = mx; __syncthreads();
    for (int o = 128; o > 0; o >>= 1) {
        if (threadIdx.x < o) sh[threadIdx.x] = fmaxf(sh[threadIdx.x], sh[threadIdx.x+o]);
        __syncthreads();
    }
    mx = sh[0]; __syncthreads();
    float sum = 0.f;
    for (int k = threadIdx.x; k < SS; k += 256) {
        float v = (sseg[k] == sq) ? sv[k]*scale : -1e9f;
        float e = expf(v - mx);
        sv[k] = e;
        sum += e;
    }
    sh[threadIdx.x] = sum; __syncthreads();
    for (int o = 128; o > 0; o >>= 1) {
        if (threadIdx.x < o) sh[threadIdx.x] += sh[threadIdx.x+o];
        __syncthreads();
    }
    float inv = 1.0f / sh[0];
    __syncthreads();
    for (int k = threadIdx.x; k < SS; k += 256) {
        float pv = sv[k] * inv;
        __nv_bfloat16 hi = __float2bfloat16_rn(pv);
        arow[k]      = hi;
        arow[SS + k] = __float2bfloat16_rn(pv - __bfloat162float(hi));
    }
}

// pooling + embeddings, writes 3-way split chunk directly
__global__ void chunk_k(const float* __restrict__ size_emb,
                        const float* __restrict__ pos_enc) {
    int m = blockIdx.x, b = blockIdx.y;
    int cnt = g_segcount[b*MAXC + m];
    int st  = g_segstart[b*MAXC + m];
    __nv_bfloat16* drow = g_chunk3 + ((size_t)b*MAXC + m) * (3*DD);
    for (int d = threadIdx.x; d < DD; d += 256) {
        float v;
        if (cnt > 0) {
            float sum = 0.f;
            for (int s = st; s < st + cnt; s++)
                sum += g_attnout[((size_t)b*SS + s)*DD + d];
            int cl = min(cnt, 1023);
            v = sum / (float)cnt + size_emb[(size_t)cl*DD + d];
        } else v = 0.f;
        v += pos_enc[(size_t)m*DD + d];
        __nv_bfloat16 h = __float2bfloat16_rn(v);
        float r1 = v - __bfloat162float(h);
        __nv_bfloat16 mm = __float2bfloat16_rn(r1);
        drow[d]        = h;
        drow[DD + d]   = mm;
        drow[2*DD + d] = __float2bfloat16_rn(r1 - __bfloat162float(mm));
    }
}

__global__ void ln_k(const float* __restrict__ gamma,
                     const float* __restrict__ beta,
                     float* __restrict__ out) {
    int r = blockIdx.x;
    const float* y = g_y + (size_t)r*DD;
    __shared__ float sh[256];
    float s = 0.f;
    for (int d = threadIdx.x; d < DD; d += 256) s += y[d];
    sh[threadIdx.x] = s; __syncthreads();
    for (int o = 128; o > 0; o >>= 1) {
        if (threadIdx.x < o) sh[threadIdx.x] += sh[threadIdx.x+o];
        __syncthreads();
    }
    float mu = sh[0] / (float)DD; __syncthreads();
    float v2 = 0.f;
    for (int d = threadIdx.x; d < DD; d += 256) { float t = y[d]-mu; v2 += t*t; }
    sh[threadIdx.x] = v2; __syncthreads();
    for (int o = 128; o > 0; o >>= 1) {
        if (threadIdx.x < o) sh[threadIdx.x] += sh[threadIdx.x+o];
        __syncthreads();
    }
    float inv = 1.0f / sqrtf(sh[0] / (float)DD + 1e-5f);
    for (int d = threadIdx.x; d < DD; d += 256)
        out[(size_t)r*DD + d] = (y[d] - mu) * inv * gamma[d] + beta[d];
}

// ---------------- host launchers ----------------
struct GemmArgs {
    const __nv_bfloat16 *A, *B;
    const float* bias;
    float* C;
    __nv_bfloat16* C3;
    int M, N, K, lda, ldb, ldc, segoff;
    long long sAi, sAo, sBi, sBo, sCi, sCo, sbias;
    int innerN, batch;
};

template<int NP, int ACT, int OMODE>
static void tg_launch(const GemmArgs& a) {
    dim3 grid(a.N/128, (a.M + 127)/128, a.batch);
    tgemm_k<NP,ACT,OMODE><<<grid,256,TG_SMEM>>>(a.A, a.B, a.bias, a.C, a.C3,
        a.M, a.K, a.lda, a.ldb, a.ldc, a.segoff,
        a.sAi, a.sAo, a.sBi, a.sBo, a.sCi, a.sCo, a.sbias, a.innerN);
}

static void split3(const float* src, __nv_bfloat16* dst, long long rows, int cols) {
    long long total = rows * cols;
    split3_k<<<(unsigned)((total + 255)/256), 256>>>(src, dst, total, cols);
}

extern "C" void kernel_launch(void* const* d_in, const int* in_sizes, int n_in,
                              void* d_out, int out_size) {
    const float* x         = (const float*)d_in[0];
    const float* Wp        = (const float*)d_in[1];
    const float* bp        = (const float*)d_in[2];
    const float* detW1     = (const float*)d_in[3];
    const float* detb1     = (const float*)d_in[4];
    const float* detW2     = (const float*)d_in[5];
    const float* detb2     = (const float*)d_in[6];
    const float* detW3     = (const float*)d_in[7];
    const float* detb3     = (const float*)d_in[8];
    const float* in_proj_w = (const float*)d_in[9];
    const float* in_proj_b = (const float*)d_in[10];
    const float* out_w     = (const float*)d_in[11];
    const float* out_b     = (const float*)d_in[12];
    const float* size_emb  = (const float*)d_in[13];
    const float* pos_enc   = (const float*)d_in[14];
    const float* procW1    = (const float*)d_in[15];
    const float* procb1    = (const float*)d_in[16];
    const float* procW2    = (const float*)d_in[17];
    const float* procb2    = (const float*)d_in[18];
    const float* ln_g      = (const float*)d_in[19];
    const float* ln_b      = (const float*)d_in[20];
    float* outp = (float*)d_out;

    cudaFuncSetAttribute(tgemm_k<6,0,0>, cudaFuncAttributeMaxDynamicSharedMemorySize, TG_SMEM);
    cudaFuncSetAttribute(tgemm_k<6,1,0>, cudaFuncAttributeMaxDynamicSharedMemorySize, TG_SMEM);
    cudaFuncSetAttribute(tgemm_k<6,1,1>, cudaFuncAttributeMaxDynamicSharedMemorySize, TG_SMEM);
    cudaFuncSetAttribute(tgemm_k<3,0,0>, cudaFuncAttributeMaxDynamicSharedMemorySize, TG_SMEM);
    cudaFuncSetAttribute(tgemm_k<3,0,1>, cudaFuncAttributeMaxDynamicSharedMemorySize, TG_SMEM);
    cudaFuncSetAttribute(tgemm_k<3,1,1>, cudaFuncAttributeMaxDynamicSharedMemorySize, TG_SMEM);

    void *p;
    cudaGetSymbolAddress(&p, g_xling);   float* xling   = (float*)p;
    cudaGetSymbolAddress(&p, g_h2);      float* h2      = (float*)p;
    cudaGetSymbolAddress(&p, g_qkv);     float* qkv     = (float*)p;
    cudaGetSymbolAddress(&p, g_scores);  float* scores  = (float*)p;
    cudaGetSymbolAddress(&p, g_attnout); float* attnout = (float*)p;
    cudaGetSymbolAddress(&p, g_y);       float* yb      = (float*)p;
    cudaGetSymbolAddress(&p, g_x3);      __nv_bfloat16* x3      = (__nv_bfloat16*)p;
    cudaGetSymbolAddress(&p, g_Wp3);     __nv_bfloat16* Wp3     = (__nv_bfloat16*)p;
    cudaGetSymbolAddress(&p, g_bi3);     __nv_bfloat16* bi3     = (__nv_bfloat16*)p;
    cudaGetSymbolAddress(&p, g_detW1_3); __nv_bfloat16* dW1_3   = (__nv_bfloat16*)p;
    cudaGetSymbolAddress(&p, g_h1_3);    __nv_bfloat16* h1_3    = (__nv_bfloat16*)p;
    cudaGetSymbolAddress(&p, g_detW2_3); __nv_bfloat16* dW2_3   = (__nv_bfloat16*)p;
    cudaGetSymbolAddress(&p, g_wqkv3);   __nv_bfloat16* wqkv3   = (__nv_bfloat16*)p;
    cudaGetSymbolAddress(&p, g_ctx3);    __nv_bfloat16* ctx3    = (__nv_bfloat16*)p;
    cudaGetSymbolAddress(&p, g_outw3);   __nv_bfloat16* outw3   = (__nv_bfloat16*)p;
    cudaGetSymbolAddress(&p, g_chunk3);  __nv_bfloat16* chunk3  = (__nv_bfloat16*)p;
    cudaGetSymbolAddress(&p, g_pw1_3);   __nv_bfloat16* pw1_3   = (__nv_bfloat16*)p;
    cudaGetSymbolAddress(&p, g_hproc3);  __nv_bfloat16* hproc3  = (__nv_bfloat16*)p;
    cudaGetSymbolAddress(&p, g_pw2_3);   __nv_bfloat16* pw2_3   = (__nv_bfloat16*)p;
    cudaGetSymbolAddress(&p, g_q2);      __nv_bfloat16* q2      = (__nv_bfloat16*)p;
    cudaGetSymbolAddress(&p, g_k2);      __nv_bfloat16* k2      = (__nv_bfloat16*)p;
    cudaGetSymbolAddress(&p, g_vT2);     __nv_bfloat16* vT2     = (__nv_bfloat16*)p;
    cudaGetSymbolAddress(&p, g_attn2);   __nv_bfloat16* attn2   = (__nv_bfloat16*)p;

    // ===== input splits =====
    split3(x, x3, NB*SS, DD);
    split3(Wp, Wp3, DD, DD);
    split3(detW1, dW1_3, 3*DD, 2*DD);
    split3(detW2, dW2_3, 3*(DD/2), DD);
    split3(in_proj_w, wqkv3, 3*DD, DD);
    split3(out_w, outw3, DD, DD);
    split3(procW1, pw1_3, 2*DD, DD);
    split3(procW2, pw2_3, DD, 2*DD);
    {
        long long total8 = (long long)ROWS_DET * (3*2*DD) / 8;
        bi3_k<<<(unsigned)((total8 + 255)/256), 256>>>();
    }

    // ===== boundary path (6-product) =====
    { GemmArgs a = { x3, Wp3, bp, xling, nullptr, NB*SS, DD, DD, 3*DD, 3*DD, DD, 0,
                     0,0,0,0,0,0,0, 1, 1 };
      tg_launch<6,0,0>(a); }
    norm_k<<<NB*SS, 256>>>();
    cos_k<<<dim3(CS_TOT, NB), 256>>>();
    base_k<<<(NB*SM1 + 255)/256, 256>>>();
    // h1 = gelu(bi @ detW1[n]^T + b) -> 3-way split directly
    { GemmArgs a = { bi3, dW1_3, detb1, nullptr, h1_3, ROWS_DET, DD, 2*DD,
                     3*2*DD, 3*2*DD, 3*DD, DD,
                     0, 0, (long long)DD*3*2*DD, 0,
                     (long long)ROWS_DET*3*DD, 0, DD, 3, 3 };
      tg_launch<6,1,1>(a); }
    // h2 = gelu(h1 @ detW2[n]^T + b) fp32
    { GemmArgs a = { h1_3, dW2_3, detb2, h2, nullptr, ROWS_DET, DD/2, DD,
                     3*DD, 3*DD, DD/2, 0,
                     (long long)ROWS_DET*3*DD, 0, (long long)(DD/2)*3*DD, 0,
                     (long long)ROWS_DET*(DD/2), 0, DD/2, 3, 3 };
      tg_launch<6,1,0>(a); }
    learned_final_k<<<ROWS_DET, 256>>>(detW3, detb3);
    seg_k<<<1, NB>>>();

    // ===== continuous path (3-product) =====
    { GemmArgs a = { x3, wqkv3, in_proj_b, qkv, nullptr, NB*SS, 3*DD, DD,
                     3*DD, 3*DD, 3*DD, 0, 0,0,0,0,0,0,0, 1, 1 };
      tg_launch<3,0,0>(a); }
    {
        long long t = (long long)NB*NH*SS*HDIM;
        split_qk_k<<<(unsigned)((t+255)/256), 256>>>();
        split_vT_k<<<(unsigned)((t+255)/256), 256>>>();
    }
    // scores[z] = q_z @ k_z^T
    { GemmArgs a = { q2, k2, nullptr, scores, nullptr, SS, SS, HDIM,
                     2*HDIM, 2*HDIM, SS, 0,
                     (long long)SS*2*HDIM, (long long)NH*SS*2*HDIM,
                     (long long)SS*2*HDIM, (long long)NH*SS*2*HDIM,
                     (long long)SS*SS, (long long)NH*SS*SS, 0, NH, NB*NH };
      tg_launch<3,0,0>(a); }
    softmax_k<<<dim3(SS, NB*NH), 256>>>();
    // ctx[z] = attn_z @ v_z -> 3-way split directly (layout [b,s][3*DD], inner offset h*HDIM)
    { GemmArgs a = { attn2, vT2, nullptr, nullptr, ctx3, SS, HDIM, SS,
                     2*SS, 2*SS, 3*DD, DD,
                     (long long)SS*2*SS, (long long)NH*SS*2*SS,
                     (long long)HDIM*2*SS, (long long)NH*HDIM*2*SS,
                     (long long)HDIM, (long long)SS*3*DD, 0, NH, NB*NH };
      tg_launch<3,0,1>(a); }
    // attn_out = ctx @ out_w^T + out_b
    { GemmArgs a = { ctx3, outw3, out_b, attnout, nullptr, NB*SS, DD, DD,
                     3*DD, 3*DD, DD, 0, 0,0,0,0,0,0,0, 1, 1 };
      tg_launch<3,0,0>(a); }
    chunk_k<<<dim3(MAXC, NB), 256>>>(size_emb, pos_enc);
    // hproc = gelu(chunk @ procW1^T + b) -> 3-way split directly
    { GemmArgs a = { chunk3, pw1_3, procb1, nullptr, hproc3, NB*MAXC, 2*DD, DD,
                     3*DD, 3*DD, 3*2*DD, 2*DD, 0,0,0,0,0,0,0, 1, 1 };
      tg_launch<3,1,1>(a); }
    // y = hproc @ procW2^T + b
    { GemmArgs a = { hproc3, pw2_3, procb2, yb, nullptr, NB*MAXC, DD, 2*DD,
                     3*2*DD, 3*2*DD, DD, 0, 0,0,0,0,0,0,0, 1, 1 };
      tg_launch<3,0,0>(a); }
    ln_k<<<NB*MAXC, 256>>>(ln_g, ln_b, outp);
}

// round 6
// speedup vs baseline: 1.5918x; 1.4153x over previous
#include <cuda_runtime.h>
#include <cuda_fp16.h>
#include <math.h>
#include <stdint.h>

// ---------------- problem constants ----------------
#define NB 4
#define SS 1024
#define DD 1536
#define NH 12
#define HDIM 128
#define MAXC 256
#define SM1 1023
#define ROWS_DET (NB*SM1)        // 4092
#define CS_TOT (1023+511+255)    // 1789

#define WSCALE 64.0f
#define OSINV  0.015625f         // 1/64

// ---------------- fp32 scratch ----------------
__device__ float g_xling[(size_t)NB*SS*DD];
__device__ float g_norm[NB*SS];
__device__ float g_cs[NB*CS_TOT];
__device__ float g_base[NB*SM1];
__device__ float g_h2[(size_t)3*ROWS_DET*(DD/2)];
__device__ float g_final[NB*SM1];
__device__ int   g_seg[NB*SS];
__device__ int   g_segstart[NB*MAXC];
__device__ int   g_segcount[NB*MAXC];
__device__ float g_qkv[(size_t)NB*SS*3*DD];
__device__ float g_scores[(size_t)NB*NH*SS*SS];
__device__ float g_attnout[(size_t)NB*SS*DD];
__device__ float g_y[(size_t)NB*MAXC*DD];

// ---------------- fp16 2-way split scratch [rows][2K] (hi|lo) ----------------
__device__ __half g_x2[(size_t)NB*SS*2*DD];
__device__ __half g_Wp2[(size_t)DD*2*DD];
__device__ __half g_bi2[(size_t)ROWS_DET*2*(2*DD)];
__device__ __half g_dW1_2[(size_t)3*DD*2*(2*DD)];
__device__ __half g_h1_2[(size_t)3*ROWS_DET*2*DD];
__device__ __half g_dW2_2[(size_t)3*(DD/2)*2*DD];
__device__ __half g_wqkv2[(size_t)3*DD*2*DD];
__device__ __half g_ctx2[(size_t)NB*SS*2*DD];
__device__ __half g_outw2[(size_t)DD*2*DD];
__device__ __half g_chunk2[(size_t)NB*MAXC*2*DD];
__device__ __half g_pw1_2[(size_t)2*DD*2*DD];
__device__ __half g_hproc2[(size_t)NB*MAXC*2*2*DD];
__device__ __half g_pw2_2[(size_t)DD*2*2*DD];
__device__ __half g_q2[(size_t)NB*NH*SS*2*HDIM];
__device__ __half g_k2[(size_t)NB*NH*SS*2*HDIM];
__device__ __half g_vT2[(size_t)NB*NH*HDIM*2*SS];
__device__ __half g_attn2[(size_t)NB*NH*SS*2*SS];

__device__ __forceinline__ float gelu_exact(float v) {
    return 0.5f * v * (1.0f + erff(v * 0.70710678118654752440f));
}
__device__ __forceinline__ uint32_t smem_u32(const void* p) {
    uint32_t a;
    asm("{ .reg .u64 t; cvta.to.shared.u64 t, %1; cvt.u32.u64 %0, t; }" : "=r"(a) : "l"(p));
    return a;
}

#define LDSM4(r0,r1,r2,r3,addr) \
    asm volatile("ldmatrix.sync.aligned.m8n8.x4.shared.b16 {%0,%1,%2,%3}, [%4];" \
        : "=r"(r0), "=r"(r1), "=r"(r2), "=r"(r3) : "r"(addr))

#define MMA16816(d, a, b0, b1) \
    asm volatile("mma.sync.aligned.m16n8k16.row.col.f32.f16.f16.f32 " \
        "{%0,%1,%2,%3},{%4,%5,%6,%7},{%8,%9},{%0,%1,%2,%3};" \
        : "+f"((d)[0]), "+f"((d)[1]), "+f"((d)[2]), "+f"((d)[3]) \
        : "r"((a)[0]), "r"((a)[1]), "r"((a)[2]), "r"((a)[3]), "r"(b0), "r"(b1))

#define CP_ASYNC16(dst, src, sz) \
    asm volatile("cp.async.ca.shared.global [%0], [%1], 16, %2;" :: "r"(dst), "l"(src), "r"(sz))
#define CP_COMMIT() asm volatile("cp.async.commit_group;" ::: "memory")
#define CP_WAIT1() asm volatile("cp.async.wait_group 1;" ::: "memory")
#define CP_WAIT0() asm volatile("cp.async.wait_group 0;" ::: "memory")

// ================= mma.sync fp16 split GEMM (2-stage, 2 CTAs/SM) =================
// A[M][2K] (hi|lo), B[N][2K] (hi|lo).  C = oscale * (Ah.Bh + Ah.Bl + Al.Bh) + bias
#define RSTRIDE 144
#define ATILE (128*RSTRIDE)        // 18432
#define BUFSZ (2*ATILE)            // 36864
#define TG_SMEM (2*BUFSZ)          // 73728

// OMODE: 0 = fp32 out (C); 1 = 2-way fp16 split out (C2, hi at col, lo at +segoff)
template<int ACT, int OMODE>
__global__ void __launch_bounds__(256)
tgemm_k(const __half* __restrict__ A, const __half* __restrict__ B,
        const float* __restrict__ bias, float* __restrict__ C, __half* __restrict__ C2,
        int M, int K, int lda, int ldb, int ldc, int segoff, float oscale,
        long long sAi, long long sAo, long long sBi, long long sBo,
        long long sCi, long long sCo, long long sbias, int innerN)
{
    const int segA_[3] = {0,0,1};
    const int segB_[3] = {0,1,0};
    extern __shared__ char smem[];
    uint32_t sb = smem_u32(smem);
    int tid = threadIdx.x;
    int z = blockIdx.z, zi = z % innerN, zo = z / innerN;
    A += (size_t)(zi*sAi + zo*sAo);
    B += (size_t)(zi*sBi + zo*sBo);
    if (OMODE == 0) C  += (size_t)(zi*sCi + zo*sCo);
    else            C2 += (size_t)(zi*sCi + zo*sCo);
    int m0 = blockIdx.y * 128, n0 = blockIdx.x * 128;

    const int KPC = K >> 6;
    const int NC = 3 * KPC;

    auto issue = [&](int kc, int buf) {
        int p = kc / KPC;
        int k0 = (kc - p * KPC) << 6;
        const __half* Ap = A + (size_t)segA_[p] * K + k0;
        const __half* Bp = B + (size_t)segB_[p] * K + k0;
        uint32_t sA = sb + buf * BUFSZ;
        uint32_t sB = sA + ATILE;
        #pragma unroll
        for (int i = 0; i < 4; i++) {
            int f = tid + (i << 8);
            int row = f >> 3, c = f & 7;
            int gr = m0 + row;
            int grc = gr < M ? gr : (M - 1);
            const void* src = Ap + (size_t)grc * lda + c * 8;
            uint32_t sz = gr < M ? 16u : 0u;
            CP_ASYNC16(sA + row * RSTRIDE + c * 16, src, sz);
        }
        #pragma unroll
        for (int i = 0; i < 4; i++) {
            int f = tid + (i << 8);
            int row = f >> 3, c = f & 7;
            const void* src = Bp + (size_t)(n0 + row) * ldb + c * 8;
            CP_ASYNC16(sB + row * RSTRIDE + c * 16, src, 16u);
        }
    };

    int lane = tid & 31, w = tid >> 5;
    int wm = w & 1, wn = w >> 1;
    uint32_t a_row = ((lane >> 3) & 1) * 8 + (lane & 7);
    uint32_t a_cs  = lane >> 4;
    uint32_t b_row = (lane >> 4) * 8 + (lane & 7);
    uint32_t b_cs  = (lane >> 3) & 1;

    float acc[4][4][4];
    #pragma unroll
    for (int i = 0; i < 4; i++)
        #pragma unroll
        for (int j = 0; j < 4; j++)
            #pragma unroll
            for (int r = 0; r < 4; r++) acc[i][j][r] = 0.f;

    issue(0, 0);
    CP_COMMIT();

    for (int kc = 0; kc < NC; kc++) {
        int cur = kc & 1;
        if (kc + 1 < NC) { issue(kc + 1, cur ^ 1); CP_COMMIT(); CP_WAIT1(); }
        else             { CP_WAIT0(); }
        __syncthreads();

        uint32_t sA = sb + cur * BUFSZ;
        uint32_t sB = sA + ATILE;
        #pragma unroll
        for (int ks = 0; ks < 4; ks++) {
            uint32_t av[4][4], bv[2][4];
            #pragma unroll
            for (int mt = 0; mt < 4; mt++) {
                uint32_t ad = sA + (wm*64 + mt*16 + a_row) * RSTRIDE + ((ks*2 + a_cs) << 4);
                LDSM4(av[mt][0], av[mt][1], av[mt][2], av[mt][3], ad);
            }
            #pragma unroll
            for (int bt = 0; bt < 2; bt++) {
                uint32_t bd = sB + (wn*32 + bt*16 + b_row) * RSTRIDE + ((ks*2 + b_cs) << 4);
                LDSM4(bv[bt][0], bv[bt][1], bv[bt][2], bv[bt][3], bd);
            }
            #pragma unroll
            for (int mt = 0; mt < 4; mt++)
                #pragma unroll
                for (int nt = 0; nt < 4; nt++) {
                    uint32_t b0 = bv[nt >> 1][(nt & 1) * 2];
                    uint32_t b1 = bv[nt >> 1][(nt & 1) * 2 + 1];
                    MMA16816(acc[mt][nt], av[mt], b0, b1);
                }
        }
        __syncthreads();
    }

    // ---- epilogue ----
    if (bias) bias += (size_t)z * (size_t)sbias;
    #pragma unroll
    for (int mt = 0; mt < 4; mt++) {
        int r0 = m0 + wm*64 + mt*16 + (lane >> 2);
        #pragma unroll
        for (int nt = 0; nt < 4; nt++) {
            int col = n0 + wn*32 + nt*8 + (lane & 3)*2;
            float bb0 = 0.f, bb1 = 0.f;
            if (bias) { bb0 = bias[col]; bb1 = bias[col+1]; }
            #pragma unroll
            for (int half_ = 0; half_ < 2; half_++) {
                int r = r0 + half_*8;
                if (r >= M) continue;
                float v0 = acc[mt][nt][half_*2]   * oscale + bb0;
                float v1 = acc[mt][nt][half_*2+1] * oscale + bb1;
                if (ACT == 1) { v0 = gelu_exact(v0); v1 = gelu_exact(v1); }
                if (OMODE == 0) {
                    *(float2*)(C + (size_t)r*ldc + col) = make_float2(v0, v1);
                } else {
                    __half* d = C2 + (size_t)r*ldc + col;
                    __half h0 = __float2half_rn(v0);
                    __half h1 = __float2half_rn(v1);
                    __half l0 = __float2half_rn(v0 - __half2float(h0));
                    __half l1 = __float2half_rn(v1 - __half2float(h1));
                    *(__half2*)(d)          = __halves2half2(h0, h1);
                    *(__half2*)(d + segoff) = __halves2half2(l0, l1);
                }
            }
        }
    }
}

// ================= split kernels =================
__global__ void split2_k(const float* __restrict__ src, __half* __restrict__ dst,
                         long long total, int C, float scale) {
    long long idx = (long long)blockIdx.x * 256 + threadIdx.x;
    if (idx >= total) return;
    long long r = idx / C; int c = (int)(idx % C);
    float v = src[idx] * scale;
    __half h = __float2half_rn(v);
    __half l = __float2half_rn(v - __half2float(h));
    __half* d = dst + r * (2LL*C) + c;
    d[0] = h; d[C] = l;
}

// bi2 gather: bi2[row=(b,s)][seg*2D + kk] = x2[(b, s+(kk>=D))][seg*D + kk%D]
__global__ void bi2_k() {
    long long idx = (long long)blockIdx.x * 256 + threadIdx.x;   // uint4 = 8 halfs
    const long long total = (long long)ROWS_DET * (2*2*DD) / 8;
    if (idx >= total) return;
    int row = (int)(idx / (2*2*DD/8));
    int k8  = (int)(idx % (2*2*DD/8)) * 8;
    int seg = k8 / (2*DD);
    int kk  = k8 % (2*DD);
    int b = row / SM1, s = row % SM1;
    int srow = s + (kk >= DD ? 1 : 0);
    int scol = seg*DD + (kk >= DD ? kk - DD : kk);
    const uint4* src = (const uint4*)(g_x2 + ((size_t)(b*SS + srow))*(2*DD) + scol);
    ((uint4*)g_bi2)[idx] = *src;
}

__global__ void split_qk_k() {
    long long idx = (long long)blockIdx.x * 256 + threadIdx.x;
    const long long total = (long long)NB*NH*SS*HDIM;
    if (idx >= total) return;
    int c = (int)(idx & 127);
    long long t = idx >> 7;
    int s = (int)(t & 1023);
    int z = (int)(t >> 10);
    int b = z / NH, h = z % NH;
    const float* base = g_qkv + ((size_t)(b*SS + s))*(3*DD) + h*HDIM + c;
    size_t o = ((size_t)z*SS + s) * (2*HDIM) + c;
    {
        float v = base[0];
        __half hi = __float2half_rn(v);
        g_q2[o] = hi; g_q2[o + HDIM] = __float2half_rn(v - __half2float(hi));
    }
    {
        float v = base[DD];
        __half hi = __float2half_rn(v);
        g_k2[o] = hi; g_k2[o + HDIM] = __float2half_rn(v - __half2float(hi));
    }
}

__global__ void split_vT_k() {
    long long idx = (long long)blockIdx.x * 256 + threadIdx.x;
    const long long total = (long long)NB*NH*HDIM*SS;
    if (idx >= total) return;
    int s = (int)(idx & 1023);
    long long t = idx >> 10;
    int c = (int)(t & 127);
    int z = (int)(t >> 7);
    int b = z / NH, h = z % NH;
    float v = g_qkv[((size_t)(b*SS + s))*(3*DD) + 2*DD + h*HDIM + c];
    __half hi = __float2half_rn(v);
    size_t o = ((size_t)z*HDIM + c) * (2*SS) + s;
    g_vT2[o] = hi;
    g_vT2[o + SS] = __float2half_rn(v - __half2float(hi));
}

// ---------------- small kernels ----------------
__global__ void norm_k() {
    int r = blockIdx.x;
    const float* p = g_xling + (size_t)r * DD;
    float ss = 0.f;
    for (int i = threadIdx.x; i < DD; i += 256) { float v = p[i]; ss += v*v; }
    __shared__ float sh[256];
    sh[threadIdx.x] = ss; __syncthreads();
    for (int o = 128; o > 0; o >>= 1) {
        if (threadIdx.x < o) sh[threadIdx.x] += sh[threadIdx.x + o];
        __syncthreads();
    }
    if (threadIdx.x == 0) g_norm[r] = fmaxf(sqrtf(sh[0]), 1e-8f);
}

__global__ void cos_k() {
    int b = blockIdx.y, t = blockIdx.x;
    int scale, i;
    if (t < 1023)      { scale = 1; i = t; }
    else if (t < 1534) { scale = 2; i = t - 1023; }
    else               { scale = 4; i = t - 1534; }
    int s0 = i * scale, s1 = s0 + scale;
    const float* a = g_xling + ((size_t)b*SS + s0) * DD;
    const float* c = g_xling + ((size_t)b*SS + s1) * DD;
    float d = 0.f;
    for (int j = threadIdx.x; j < DD; j += 256) d += a[j] * c[j];
    __shared__ float sh[256];
    sh[threadIdx.x] = d; __syncthreads();
    for (int o = 128; o > 0; o >>= 1) {
        if (threadIdx.x < o) sh[threadIdx.x] += sh[threadIdx.x + o];
        __syncthreads();
    }
    if (threadIdx.x == 0)
        g_cs[b*CS_TOT + t] = sh[0] / (g_norm[b*SS + s0] * g_norm[b*SS + s1]);
}

__global__ void base_k() {
    int idx = blockIdx.x * 256 + threadIdx.x;
    if (idx >= NB*SM1) return;
    int b = idx / SM1, j = idx % SM1;
    const int Ls[3]   = {1023, 511, 255};
    const int offs[3] = {0, 1023, 1534};
    float acc = 0.f;
    #pragma unroll
    for (int u = 0; u < 3; u++) {
        int L = Ls[u];
        float ratio = (float)((double)L / 1023.0);
        float src = ((float)j + 0.5f) * ratio - 0.5f;
        src = fminf(fmaxf(src, 0.0f), (float)(L - 1));
        int i0 = (int)floorf(src);
        int i1 = min(i0 + 1, L - 1);
        float w = src - (float)i0;
        const float* cs = g_cs + b*CS_TOT + offs[u];
        acc += cs[i0] * (1.0f - w) + cs[i1] * w;
    }
    g_base[idx] = 0.5f * (1.0f - acc / 3.0f);
}

__global__ void learned_final_k(const float* __restrict__ detW3,
                                const float* __restrict__ detb3) {
    int r = blockIdx.x;
    __shared__ float sh[256];
    __shared__ float sacc;
    if (threadIdx.x == 0) sacc = 0.f;
    for (int n = 0; n < 3; n++) {
        const float* h2p = g_h2 + ((size_t)n*ROWS_DET + r) * (DD/2);
        const float* w   = detW3 + n*(DD/2);
        float part = 0.f;
        for (int j = threadIdx.x; j < DD/2; j += 256) part += h2p[j] * w[j];
        __syncthreads();
        sh[threadIdx.x] = part; __syncthreads();
        for (int o = 128; o > 0; o >>= 1) {
            if (threadIdx.x < o) sh[threadIdx.x] += sh[threadIdx.x + o];
            __syncthreads();
        }
        if (threadIdx.x == 0) {
            float t = sh[0] + detb3[n];
            sacc += 1.0f / (1.0f + expf(-t));
        }
        __syncthreads();
    }
    if (threadIdx.x == 0)
        g_final[r] = 0.6f * g_base[r] + 0.4f * (sacc / 3.0f);
}

__global__ void seg_k() {
    int b = threadIdx.x;
    if (b >= NB) return;
    int cum = 0;
    for (int s = 0; s < SS; s++) {
        float bv = (s == 0) ? 1.0f : g_final[b*SM1 + s - 1];
        cum += (bv > 0.5f) ? 1 : 0;
        g_seg[b*SS + s] = cum - 1;
    }
    for (int m = 0; m < MAXC; m++) { g_segcount[b*MAXC+m] = 0; g_segstart[b*MAXC+m] = 0; }
    for (int s = 0; s < SS; s++) {
        int m = g_seg[b*SS + s];
        if (m < MAXC) {
            if (g_segcount[b*MAXC+m] == 0) g_segstart[b*MAXC+m] = s;
            g_segcount[b*MAXC+m]++;
        }
    }
}

// softmax: reads fp32 scores once, writes 2-way fp16 split probs to g_attn2
__global__ void softmax_k() {
    int z = blockIdx.y, b = z / NH, q = blockIdx.x;
    const float* row = g_scores + (size_t)z*SS*SS + (size_t)q*SS;
    __half* arow = g_attn2 + ((size_t)z*SS + q) * (2*SS);
    __shared__ float sv[SS];
    __shared__ int   sseg[SS];
    __shared__ float sh[256];
    int sq = g_seg[b*SS + q];
    const float scale = 0.088388347648318440550f;   // 1/sqrt(128)
    for (int k = threadIdx.x; k < SS; k += 256) {
        sseg[k] = g_seg[b*SS + k];
        sv[k] = row[k];
    }
    __syncthreads();
    float mx = -3.402823e38f;
    for (int k = threadIdx.x; k < SS; k += 256) {
        float v = (sseg[k] == sq) ? sv[k]*scale : -1e9f;
        mx = fmaxf(mx, v);
    }
    sh[threadIdx.x] = mx; __syncthreads();
    for (int o = 128; o > 0; o >>= 1) {
        if (threadIdx.x < o) sh[threadIdx.x] = fmaxf(sh[threadIdx.x], sh[threadIdx.x+o]);
        __syncthreads();
    }
    mx = sh[0]; __syncthreads();
    float sum = 0.f;
    for (int k = threadIdx.x; k < SS; k += 256) {
        float v = (sseg[k] == sq) ? sv[k]*scale : -1e9f;
        float e = expf(v - mx);
        sv[k] = e;
        sum += e;
    }
    sh[threadIdx.x] = sum; __syncthreads();
    for (int o = 128; o > 0; o >>= 1) {
        if (threadIdx.x < o) sh[threadIdx.x] += sh[threadIdx.x+o];
        __syncthreads();
    }
    float inv = 1.0f / sh[0];
    __syncthreads();
    for (int k = threadIdx.x; k < SS; k += 256) {
        float pv = sv[k] * inv;
        __half hi = __float2half_rn(pv);
        arow[k]      = hi;
        arow[SS + k] = __float2half_rn(pv - __half2float(hi));
    }
}

// pooling + embeddings, writes 2-way fp16 split chunk directly
__global__ void chunk_k(const float* __restrict__ size_emb,
                        const float* __restrict__ pos_enc) {
    int m = blockIdx.x, b = blockIdx.y;
    int cnt = g_segcount[b*MAXC + m];
    int st  = g_segstart[b*MAXC + m];
    __half* drow = g_chunk2 + ((size_t)b*MAXC + m) * (2*DD);
    for (int d = threadIdx.x; d < DD; d += 256) {
        float v;
        if (cnt > 0) {
            float sum = 0.f;
            for (int s = st; s < st + cnt; s++)
                sum += g_attnout[((size_t)b*SS + s)*DD + d];
            int cl = min(cnt, 1023);
            v = sum / (float)cnt + size_emb[(size_t)cl*DD + d];
        } else v = 0.f;
        v += pos_enc[(size_t)m*DD + d];
        __half h = __float2half_rn(v);
        drow[d]      = h;
        drow[DD + d] = __float2half_rn(v - __half2float(h));
    }
}

__global__ void ln_k(const float* __restrict__ gamma,
                     const float* __restrict__ beta,
                     float* __restrict__ out) {
    int r = blockIdx.x;
    const float* y = g_y + (size_t)r*DD;
    __shared__ float sh[256];
    float s = 0.f;
    for (int d = threadIdx.x; d < DD; d += 256) s += y[d];
    sh[threadIdx.x] = s; __syncthreads();
    for (int o = 128; o > 0; o >>= 1) {
        if (threadIdx.x < o) sh[threadIdx.x] += sh[threadIdx.x+o];
        __syncthreads();
    }
    float mu = sh[0] / (float)DD; __syncthreads();
    float v2 = 0.f;
    for (int d = threadIdx.x; d < DD; d += 256) { float t = y[d]-mu; v2 += t*t; }
    sh[threadIdx.x] = v2; __syncthreads();
    for (int o = 128; o > 0; o >>= 1) {
        if (threadIdx.x < o) sh[threadIdx.x] += sh[threadIdx.x+o];
        __syncthreads();
    }
    float inv = 1.0f / sqrtf(sh[0] / (float)DD + 1e-5f);
    for (int d = threadIdx.x; d < DD; d += 256)
        out[(size_t)r*DD + d] = (y[d] - mu) * inv * gamma[d] + beta[d];
}

// ---------------- host launchers ----------------
struct GemmArgs {
    const __half *A, *B;
    const float* bias;
    float* C;
    __half* C2;
    int M, N, K, lda, ldb, ldc, segoff;
    float oscale;
    long long sAi, sAo, sBi, sBo, sCi, sCo, sbias;
    int innerN, batch;
};

template<int ACT, int OMODE>
static void tg_launch(const GemmArgs& a) {
    dim3 grid(a.N/128, (a.M + 127)/128, a.batch);
    tgemm_k<ACT,OMODE><<<grid,256,TG_SMEM>>>(a.A, a.B, a.bias, a.C, a.C2,
        a.M, a.K, a.lda, a.ldb, a.ldc, a.segoff, a.oscale,
        a.sAi, a.sAo, a.sBi, a.sBo, a.sCi, a.sCo, a.sbias, a.innerN);
}

static void split2(const float* src, __half* dst, long long rows, int cols, float scale) {
    long long total = rows * cols;
    split2_k<<<(unsigned)((total + 255)/256), 256>>>(src, dst, total, cols, scale);
}

extern "C" void kernel_launch(void* const* d_in, const int* in_sizes, int n_in,
                              void* d_out, int out_size) {
    const float* x         = (const float*)d_in[0];
    const float* Wp        = (const float*)d_in[1];
    const float* bp        = (const float*)d_in[2];
    const float* detW1     = (const float*)d_in[3];
    const float* detb1     = (const float*)d_in[4];
    const float* detW2     = (const float*)d_in[5];
    const float* detb2     = (const float*)d_in[6];
    const float* detW3     = (const float*)d_in[7];
    const float* detb3     = (const float*)d_in[8];
    const float* in_proj_w = (const float*)d_in[9];
    const float* in_proj_b = (const float*)d_in[10];
    const float* out_w     = (const float*)d_in[11];
    const float* out_b     = (const float*)d_in[12];
    const float* size_emb  = (const float*)d_in[13];
    const float* pos_enc   = (const float*)d_in[14];
    const float* procW1    = (const float*)d_in[15];
    const float* procb1    = (const float*)d_in[16];
    const float* procW2    = (const float*)d_in[17];
    const float* procb2    = (const float*)d_in[18];
    const float* ln_g      = (const float*)d_in[19];
    const float* ln_b      = (const float*)d_in[20];
    float* outp = (float*)d_out;

    cudaFuncSetAttribute(tgemm_k<0,0>, cudaFuncAttributeMaxDynamicSharedMemorySize, TG_SMEM);
    cudaFuncSetAttribute(tgemm_k<1,0>, cudaFuncAttributeMaxDynamicSharedMemorySize, TG_SMEM);
    cudaFuncSetAttribute(tgemm_k<1,1>, cudaFuncAttributeMaxDynamicSharedMemorySize, TG_SMEM);
    cudaFuncSetAttribute(tgemm_k<0,1>, cudaFuncAttributeMaxDynamicSharedMemorySize, TG_SMEM);

    void *p;
    cudaGetSymbolAddress(&p, g_xling);   float* xling   = (float*)p;
    cudaGetSymbolAddress(&p, g_h2);      float* h2      = (float*)p;
    cudaGetSymbolAddress(&p, g_qkv);     float* qkv     = (float*)p;
    cudaGetSymbolAddress(&p, g_scores);  float* scores  = (float*)p;
    cudaGetSymbolAddress(&p, g_attnout); float* attnout = (float*)p;
    cudaGetSymbolAddress(&p, g_y);       float* yb      = (float*)p;
    cudaGetSymbolAddress(&p, g_x2);      __half* x2     = (__half*)p;
    cudaGetSymbolAddress(&p, g_Wp2);     __half* Wp2    = (__half*)p;
    cudaGetSymbolAddress(&p, g_bi2);     __half* bi2    = (__half*)p;
    cudaGetSymbolAddress(&p, g_dW1_2);   __half* dW1_2  = (__half*)p;
    cudaGetSymbolAddress(&p, g_h1_2);    __half* h1_2   = (__half*)p;
    cudaGetSymbolAddress(&p, g_dW2_2);   __half* dW2_2  = (__half*)p;
    cudaGetSymbolAddress(&p, g_wqkv2);   __half* wqkv2  = (__half*)p;
    cudaGetSymbolAddress(&p, g_ctx2);    __half* ctx2   = (__half*)p;
    cudaGetSymbolAddress(&p, g_outw2);   __half* outw2  = (__half*)p;
    cudaGetSymbolAddress(&p, g_chunk2);  __half* chunk2 = (__half*)p;
    cudaGetSymbolAddress(&p, g_pw1_2);   __half* pw1_2  = (__half*)p;
    cudaGetSymbolAddress(&p, g_hproc2);  __half* hproc2 = (__half*)p;
    cudaGetSymbolAddress(&p, g_pw2_2);   __half* pw2_2  = (__half*)p;
    cudaGetSymbolAddress(&p, g_q2);      __half* q2     = (__half*)p;
    cudaGetSymbolAddress(&p, g_k2);      __half* k2     = (__half*)p;
    cudaGetSymbolAddress(&p, g_vT2);     __half* vT2    = (__half*)p;
    cudaGetSymbolAddress(&p, g_attn2);   __half* attn2  = (__half*)p;

    // ===== input splits (weights scaled by 64 to keep fp16 lo plane normal) =====
    split2(x, x2, NB*SS, DD, 1.0f);
    split2(Wp, Wp2, DD, DD, WSCALE);
    split2(detW1, dW1_2, 3*DD, 2*DD, WSCALE);
    split2(detW2, dW2_2, 3*(DD/2), DD, WSCALE);
    split2(in_proj_w, wqkv2, 3*DD, DD, WSCALE);
    split2(out_w, outw2, DD, DD, WSCALE);
    split2(procW1, pw1_2, 2*DD, DD, WSCALE);
    split2(procW2, pw2_2, DD, 2*DD, WSCALE);
    {
        long long total8 = (long long)ROWS_DET * (2*2*DD) / 8;
        bi2_k<<<(unsigned)((total8 + 255)/256), 256>>>();
    }

    // ===== boundary path (fp16 3-product ~ fp32 accuracy) =====
    { GemmArgs a = { x2, Wp2, bp, xling, nullptr, NB*SS, DD, DD, 2*DD, 2*DD, DD, 0,
                     OSINV, 0,0,0,0,0,0,0, 1, 1 };
      tg_launch<0,0>(a); }
    norm_k<<<NB*SS, 256>>>();
    cos_k<<<dim3(CS_TOT, NB), 256>>>();
    base_k<<<(NB*SM1 + 255)/256, 256>>>();
    // h1 = gelu(bi @ detW1[n]^T + b) -> 2-way split directly
    { GemmArgs a = { bi2, dW1_2, detb1, nullptr, h1_2, ROWS_DET, DD, 2*DD,
                     2*2*DD, 2*2*DD, 2*DD, DD, OSINV,
                     0, 0, (long long)DD*2*2*DD, 0,
                     (long long)ROWS_DET*2*DD, 0, DD, 3, 3 };
      tg_launch<1,1>(a); }
    // h2 = gelu(h1 @ detW2[n]^T + b) fp32
    { GemmArgs a = { h1_2, dW2_2, detb2, h2, nullptr, ROWS_DET, DD/2, DD,
                     2*DD, 2*DD, DD/2, 0, OSINV,
                     (long long)ROWS_DET*2*DD, 0, (long long)(DD/2)*2*DD, 0,
                     (long long)ROWS_DET*(DD/2), 0, DD/2, 3, 3 };
      tg_launch<1,0>(a); }
    learned_final_k<<<ROWS_DET, 256>>>(detW3, detb3);
    seg_k<<<1, NB>>>();

    // ===== continuous path =====
    { GemmArgs a = { x2, wqkv2, in_proj_b, qkv, nullptr, NB*SS, 3*DD, DD,
                     2*DD, 2*DD, 3*DD, 0, OSINV, 0,0,0,0,0,0,0, 1, 1 };
      tg_launch<0,0>(a); }
    {
        long long t = (long long)NB*NH*SS*HDIM;
        split_qk_k<<<(unsigned)((t+255)/256), 256>>>();
        split_vT_k<<<(unsigned)((t+255)/256), 256>>>();
    }
    // scores[z] = q_z @ k_z^T
    { GemmArgs a = { q2, k2, nullptr, scores, nullptr, SS, SS, HDIM,
                     2*HDIM, 2*HDIM, SS, 0, 1.0f,
                     (long long)SS*2*HDIM, (long long)NH*SS*2*HDIM,
                     (long long)SS*2*HDIM, (long long)NH*SS*2*HDIM,
                     (long long)SS*SS, (long long)NH*SS*SS, 0, NH, NB*NH };
      tg_launch<0,0>(a); }
    softmax_k<<<dim3(SS, NB*NH), 256>>>();
    // ctx[z] = attn_z @ v_z -> 2-way split out, layout [b,s][2*DD], head offset inside planes
    { GemmArgs a = { attn2, vT2, nullptr, nullptr, ctx2, SS, HDIM, SS,
                     2*SS, 2*SS, 2*DD, DD, 1.0f,
                     (long long)SS*2*SS, (long long)NH*SS*2*SS,
                     (long long)HDIM*2*SS, (long long)NH*HDIM*2*SS,
                     (long long)HDIM, (long long)SS*2*DD, 0, NH, NB*NH };
      tg_launch<0,1>(a); }
    // attn_out = ctx @ out_w^T + out_b
    { GemmArgs a = { ctx2, outw2, out_b, attnout, nullptr, NB*SS, DD, DD,
                     2*DD, 2*DD, DD, 0, OSINV, 0,0,0,0,0,0,0, 1, 1 };
      tg_launch<0,0>(a); }
    chunk_k<<<dim3(MAXC, NB), 256>>>(size_emb, pos_enc);
    // hproc = gelu(chunk @ procW1^T + b) -> 2-way split directly
    { GemmArgs a = { chunk2, pw1_2, procb1, nullptr, hproc2, NB*MAXC, 2*DD, DD,
                     2*DD, 2*DD, 2*2*DD, 2*DD, OSINV, 0,0,0,0,0,0,0, 1, 1 };
      tg_launch<1,1>(a); }
    // y = hproc @ procW2^T + b
    { GemmArgs a = { hproc2, pw2_2, procb2, yb, nullptr, NB*MAXC, DD, 2*DD,
                     2*2*DD, 2*2*DD, DD, 0, OSINV, 0,0,0,0,0,0,0, 1, 1 };
      tg_launch<0,0>(a); }
    ln_k<<<NB*MAXC, 256>>>(ln_g, ln_b, outp);
}

// round 7
// speedup vs baseline: 1.8281x; 1.1485x over previous
#include <cuda_runtime.h>
#include <cuda_fp16.h>
#include <math.h>
#include <stdint.h>

// ---------------- problem constants ----------------
#define NB 4
#define SS 1024
#define DD 1536
#define NH 12
#define HDIM 128
#define MAXC 256
#define SM1 1023
#define ROWS_DET (NB*SM1)        // 4092
#define CS_TOT (1023+511+255)    // 1789

#define WSCALE 64.0f
#define OSINV  0.015625f         // 1/64

// ---------------- fp32 scratch ----------------
__device__ float g_xling[(size_t)NB*SS*DD];
__device__ float g_norm[NB*SS];
__device__ float g_cs[NB*CS_TOT];
__device__ float g_base[NB*SM1];
__device__ float g_h2[(size_t)3*ROWS_DET*(DD/2)];
__device__ float g_final[NB*SM1];
__device__ int   g_seg[NB*SS];
__device__ int   g_qlo[NB*SS];
__device__ int   g_qhi[NB*SS];
__device__ int   g_segstart[NB*MAXC];
__device__ int   g_segcount[NB*MAXC];
__device__ float g_qkv[(size_t)NB*SS*3*DD];
__device__ float g_attnout[(size_t)NB*SS*DD];
__device__ float g_y[(size_t)NB*MAXC*DD];

// ---------------- fp16 2-way split scratch [rows][2K] (hi|lo) ----------------
__device__ __half g_x2[(size_t)NB*SS*2*DD];
__device__ __half g_Wp2[(size_t)DD*2*DD];
__device__ __half g_bi2[(size_t)ROWS_DET*2*(2*DD)];
__device__ __half g_dW1_2[(size_t)3*DD*2*(2*DD)];
__device__ __half g_h1_2[(size_t)3*ROWS_DET*2*DD];
__device__ __half g_dW2_2[(size_t)3*(DD/2)*2*DD];
__device__ __half g_wqkv2[(size_t)3*DD*2*DD];
__device__ __half g_ctx2[(size_t)NB*SS*2*DD];
__device__ __half g_outw2[(size_t)DD*2*DD];
__device__ __half g_chunk2[(size_t)NB*MAXC*2*DD];
__device__ __half g_pw1_2[(size_t)2*DD*2*DD];
__device__ __half g_hproc2[(size_t)NB*MAXC*2*2*DD];
__device__ __half g_pw2_2[(size_t)DD*2*2*DD];

__device__ __forceinline__ float gelu_exact(float v) {
    return 0.5f * v * (1.0f + erff(v * 0.70710678118654752440f));
}
__device__ __forceinline__ uint32_t smem_u32(const void* p) {
    uint32_t a;
    asm("{ .reg .u64 t; cvta.to.shared.u64 t, %1; cvt.u32.u64 %0, t; }" : "=r"(a) : "l"(p));
    return a;
}

#define LDSM4(r0,r1,r2,r3,addr) \
    asm volatile("ldmatrix.sync.aligned.m8n8.x4.shared.b16 {%0,%1,%2,%3}, [%4];" \
        : "=r"(r0), "=r"(r1), "=r"(r2), "=r"(r3) : "r"(addr))

#define MMA16816(d, a, b0, b1) \
    asm volatile("mma.sync.aligned.m16n8k16.row.col.f32.f16.f16.f32 " \
        "{%0,%1,%2,%3},{%4,%5,%6,%7},{%8,%9},{%0,%1,%2,%3};" \
        : "+f"((d)[0]), "+f"((d)[1]), "+f"((d)[2]), "+f"((d)[3]) \
        : "r"((a)[0]), "r"((a)[1]), "r"((a)[2]), "r"((a)[3]), "r"(b0), "r"(b1))

#define CP_ASYNC16(dst, src, sz) \
    asm volatile("cp.async.ca.shared.global [%0], [%1], 16, %2;" :: "r"(dst), "l"(src), "r"(sz))
#define CP_COMMIT() asm volatile("cp.async.commit_group;" ::: "memory")
#define CP_WAIT1() asm volatile("cp.async.wait_group 1;" ::: "memory")
#define CP_WAIT0() asm volatile("cp.async.wait_group 0;" ::: "memory")

// ================= mma.sync fp16 split GEMM (2-stage, 2 CTAs/SM) =================
// A[M][2K] (hi|lo), B[N][2K] (hi|lo).  C = oscale * (Ah.Bh + Ah.Bl + Al.Bh) + bias
#define RSTRIDE 144
#define ATILE (128*RSTRIDE)        // 18432
#define BUFSZ (2*ATILE)            // 36864
#define TG_SMEM (2*BUFSZ)          // 73728

// OMODE: 0 = fp32 out (C); 1 = 2-way fp16 split out (C2, hi at col, lo at +segoff)
template<int ACT, int OMODE>
__global__ void __launch_bounds__(256)
tgemm_k(const __half* __restrict__ A, const __half* __restrict__ B,
        const float* __restrict__ bias, float* __restrict__ C, __half* __restrict__ C2,
        int M, int K, int lda, int ldb, int ldc, int segoff, float oscale,
        long long sAi, long long sAo, long long sBi, long long sBo,
        long long sCi, long long sCo, long long sbias, int innerN)
{
    const int segA_[3] = {0,0,1};
    const int segB_[3] = {0,1,0};
    extern __shared__ char smem[];
    uint32_t sb = smem_u32(smem);
    int tid = threadIdx.x;
    int z = blockIdx.z, zi = z % innerN, zo = z / innerN;
    A += (size_t)(zi*sAi + zo*sAo);
    B += (size_t)(zi*sBi + zo*sBo);
    if (OMODE == 0) C  += (size_t)(zi*sCi + zo*sCo);
    else            C2 += (size_t)(zi*sCi + zo*sCo);
    int m0 = blockIdx.y * 128, n0 = blockIdx.x * 128;

    const int KPC = K >> 6;
    const int NC = 3 * KPC;

    auto issue = [&](int kc, int buf) {
        int p = kc / KPC;
        int k0 = (kc - p * KPC) << 6;
        const __half* Ap = A + (size_t)segA_[p] * K + k0;
        const __half* Bp = B + (size_t)segB_[p] * K + k0;
        uint32_t sA = sb + buf * BUFSZ;
        uint32_t sB = sA + ATILE;
        #pragma unroll
        for (int i = 0; i < 4; i++) {
            int f = tid + (i << 8);
            int row = f >> 3, c = f & 7;
            int gr = m0 + row;
            int grc = gr < M ? gr : (M - 1);
            const void* src = Ap + (size_t)grc * lda + c * 8;
            uint32_t sz = gr < M ? 16u : 0u;
            CP_ASYNC16(sA + row * RSTRIDE + c * 16, src, sz);
        }
        #pragma unroll
        for (int i = 0; i < 4; i++) {
            int f = tid + (i << 8);
            int row = f >> 3, c = f & 7;
            const void* src = Bp + (size_t)(n0 + row) * ldb + c * 8;
            CP_ASYNC16(sB + row * RSTRIDE + c * 16, src, 16u);
        }
    };

    int lane = tid & 31, w = tid >> 5;
    int wm = w & 1, wn = w >> 1;
    uint32_t a_row = ((lane >> 3) & 1) * 8 + (lane & 7);
    uint32_t a_cs  = lane >> 4;
    uint32_t b_row = (lane >> 4) * 8 + (lane & 7);
    uint32_t b_cs  = (lane >> 3) & 1;

    float acc[4][4][4];
    #pragma unroll
    for (int i = 0; i < 4; i++)
        #pragma unroll
        for (int j = 0; j < 4; j++)
            #pragma unroll
            for (int r = 0; r < 4; r++) acc[i][j][r] = 0.f;

    issue(0, 0);
    CP_COMMIT();

    for (int kc = 0; kc < NC; kc++) {
        int cur = kc & 1;
        if (kc + 1 < NC) { issue(kc + 1, cur ^ 1); CP_COMMIT(); CP_WAIT1(); }
        else             { CP_WAIT0(); }
        __syncthreads();

        uint32_t sA = sb + cur * BUFSZ;
        uint32_t sB = sA + ATILE;
        #pragma unroll
        for (int ks = 0; ks < 4; ks++) {
            uint32_t av[4][4], bv[2][4];
            #pragma unroll
            for (int mt = 0; mt < 4; mt++) {
                uint32_t ad = sA + (wm*64 + mt*16 + a_row) * RSTRIDE + ((ks*2 + a_cs) << 4);
                LDSM4(av[mt][0], av[mt][1], av[mt][2], av[mt][3], ad);
            }
            #pragma unroll
            for (int bt = 0; bt < 2; bt++) {
                uint32_t bd = sB + (wn*32 + bt*16 + b_row) * RSTRIDE + ((ks*2 + b_cs) << 4);
                LDSM4(bv[bt][0], bv[bt][1], bv[bt][2], bv[bt][3], bd);
            }
            #pragma unroll
            for (int mt = 0; mt < 4; mt++)
                #pragma unroll
                for (int nt = 0; nt < 4; nt++) {
                    uint32_t b0 = bv[nt >> 1][(nt & 1) * 2];
                    uint32_t b1 = bv[nt >> 1][(nt & 1) * 2 + 1];
                    MMA16816(acc[mt][nt], av[mt], b0, b1);
                }
        }
        __syncthreads();
    }

    // ---- epilogue ----
    if (bias) bias += (size_t)z * (size_t)sbias;
    #pragma unroll
    for (int mt = 0; mt < 4; mt++) {
        int r0 = m0 + wm*64 + mt*16 + (lane >> 2);
        #pragma unroll
        for (int nt = 0; nt < 4; nt++) {
            int col = n0 + wn*32 + nt*8 + (lane & 3)*2;
            float bb0 = 0.f, bb1 = 0.f;
            if (bias) { bb0 = bias[col]; bb1 = bias[col+1]; }
            #pragma unroll
            for (int half_ = 0; half_ < 2; half_++) {
                int r = r0 + half_*8;
                if (r >= M) continue;
                float v0 = acc[mt][nt][half_*2]   * oscale + bb0;
                float v1 = acc[mt][nt][half_*2+1] * oscale + bb1;
                if (ACT == 1) { v0 = gelu_exact(v0); v1 = gelu_exact(v1); }
                if (OMODE == 0) {
                    *(float2*)(C + (size_t)r*ldc + col) = make_float2(v0, v1);
                } else {
                    __half* d = C2 + (size_t)r*ldc + col;
                    __half h0 = __float2half_rn(v0);
                    __half h1 = __float2half_rn(v1);
                    __half l0 = __float2half_rn(v0 - __half2float(h0));
                    __half l1 = __float2half_rn(v1 - __half2float(h1));
                    *(__half2*)(d)          = __halves2half2(h0, h1);
                    *(__half2*)(d + segoff) = __halves2half2(l0, l1);
                }
            }
        }
    }
}

// ================= split kernels =================
__global__ void split2_k(const float* __restrict__ src, __half* __restrict__ dst,
                         long long total, int C, float scale) {
    long long idx = (long long)blockIdx.x * 256 + threadIdx.x;
    if (idx >= total) return;
    long long r = idx / C; int c = (int)(idx % C);
    float v = src[idx] * scale;
    __half h = __float2half_rn(v);
    __half l = __float2half_rn(v - __half2float(h));
    __half* d = dst + r * (2LL*C) + c;
    d[0] = h; d[C] = l;
}

// bi2 gather: bi2[row=(b,s)][seg*2D + kk] = x2[(b, s+(kk>=D))][seg*D + kk%D]
__global__ void bi2_k() {
    long long idx = (long long)blockIdx.x * 256 + threadIdx.x;   // uint4 = 8 halfs
    const long long total = (long long)ROWS_DET * (2*2*DD) / 8;
    if (idx >= total) return;
    int row = (int)(idx / (2*2*DD/8));
    int k8  = (int)(idx % (2*2*DD/8)) * 8;
    int seg = k8 / (2*DD);
    int kk  = k8 % (2*DD);
    int b = row / SM1, s = row % SM1;
    int srow = s + (kk >= DD ? 1 : 0);
    int scol = seg*DD + (kk >= DD ? kk - DD : kk);
    const uint4* src = (const uint4*)(g_x2 + ((size_t)(b*SS + srow))*(2*DD) + scol);
    ((uint4*)g_bi2)[idx] = *src;
}

// ---------------- small kernels ----------------
__global__ void norm_k() {
    int r = blockIdx.x;
    const float* p = g_xling + (size_t)r * DD;
    float ss = 0.f;
    for (int i = threadIdx.x; i < DD; i += 256) { float v = p[i]; ss += v*v; }
    __shared__ float sh[256];
    sh[threadIdx.x] = ss; __syncthreads();
    for (int o = 128; o > 0; o >>= 1) {
        if (threadIdx.x < o) sh[threadIdx.x] += sh[threadIdx.x + o];
        __syncthreads();
    }
    if (threadIdx.x == 0) g_norm[r] = fmaxf(sqrtf(sh[0]), 1e-8f);
}

__global__ void cos_k() {
    int b = blockIdx.y, t = blockIdx.x;
    int scale, i;
    if (t < 1023)      { scale = 1; i = t; }
    else if (t < 1534) { scale = 2; i = t - 1023; }
    else               { scale = 4; i = t - 1534; }
    int s0 = i * scale, s1 = s0 + scale;
    const float* a = g_xling + ((size_t)b*SS + s0) * DD;
    const float* c = g_xling + ((size_t)b*SS + s1) * DD;
    float d = 0.f;
    for (int j = threadIdx.x; j < DD; j += 256) d += a[j] * c[j];
    __shared__ float sh[256];
    sh[threadIdx.x] = d; __syncthreads();
    for (int o = 128; o > 0; o >>= 1) {
        if (threadIdx.x < o) sh[threadIdx.x] += sh[threadIdx.x + o];
        __syncthreads();
    }
    if (threadIdx.x == 0)
        g_cs[b*CS_TOT + t] = sh[0] / (g_norm[b*SS + s0] * g_norm[b*SS + s1]);
}

__global__ void base_k() {
    int idx = blockIdx.x * 256 + threadIdx.x;
    if (idx >= NB*SM1) return;
    int b = idx / SM1, j = idx % SM1;
    const int Ls[3]   = {1023, 511, 255};
    const int offs[3] = {0, 1023, 1534};
    float acc = 0.f;
    #pragma unroll
    for (int u = 0; u < 3; u++) {
        int L = Ls[u];
        float ratio = (float)((double)L / 1023.0);
        float src = ((float)j + 0.5f) * ratio - 0.5f;
        src = fminf(fmaxf(src, 0.0f), (float)(L - 1));
        int i0 = (int)floorf(src);
        int i1 = min(i0 + 1, L - 1);
        float w = src - (float)i0;
        const float* cs = g_cs + b*CS_TOT + offs[u];
        acc += cs[i0] * (1.0f - w) + cs[i1] * w;
    }
    g_base[idx] = 0.5f * (1.0f - acc / 3.0f);
}

__global__ void learned_final_k(const float* __restrict__ detW3,
                                const float* __restrict__ detb3) {
    int r = blockIdx.x;
    __shared__ float sh[256];
    __shared__ float sacc;
    if (threadIdx.x == 0) sacc = 0.f;
    for (int n = 0; n < 3; n++) {
        const float* h2p = g_h2 + ((size_t)n*ROWS_DET + r) * (DD/2);
        const float* w   = detW3 + n*(DD/2);
        float part = 0.f;
        for (int j = threadIdx.x; j < DD/2; j += 256) part += h2p[j] * w[j];
        __syncthreads();
        sh[threadIdx.x] = part; __syncthreads();
        for (int o = 128; o > 0; o >>= 1) {
            if (threadIdx.x < o) sh[threadIdx.x] += sh[threadIdx.x + o];
            __syncthreads();
        }
        if (threadIdx.x == 0) {
            float t = sh[0] + detb3[n];
            sacc += 1.0f / (1.0f + expf(-t));
        }
        __syncthreads();
    }
    if (threadIdx.x == 0)
        g_final[r] = 0.6f * g_base[r] + 0.4f * (sacc / 3.0f);
}

// segmentation + per-position segment ranges
__global__ void seg_k() {
    int b = threadIdx.x;
    if (b >= NB) return;
    int cum = 0;
    for (int s = 0; s < SS; s++) {
        float bv = (s == 0) ? 1.0f : g_final[b*SM1 + s - 1];
        cum += (bv > 0.5f) ? 1 : 0;
        g_seg[b*SS + s] = cum - 1;
    }
    for (int m = 0; m < MAXC; m++) { g_segcount[b*MAXC+m] = 0; g_segstart[b*MAXC+m] = 0; }
    for (int s = 0; s < SS; s++) {
        int m = g_seg[b*SS + s];
        if (m < MAXC) {
            if (g_segcount[b*MAXC+m] == 0) g_segstart[b*MAXC+m] = s;
            g_segcount[b*MAXC+m]++;
        }
    }
    // per-position [lo, hi) of own segment (segments are contiguous runs)
    int start = 0;
    for (int s = 0; s < SS; s++) {
        if (s > 0 && g_seg[b*SS + s] != g_seg[b*SS + s - 1]) start = s;
        g_qlo[b*SS + s] = start;
    }
    int end = SS;
    for (int s = SS - 1; s >= 0; s--) {
        if (s < SS - 1 && g_seg[b*SS + s] != g_seg[b*SS + s + 1]) end = s + 1;
        g_qhi[b*SS + s] = end;
    }
}

// fused segment attention: one warp per (b, s, h); fp32; writes fp16-split ctx
__global__ void __launch_bounds__(256)
seg_attn_k() {
    __shared__ float dots[8][SS];
    int w = threadIdx.x >> 5, lane = threadIdx.x & 31;
    int g = blockIdx.x * 8 + w;
    int h = g % NH;
    int s = (g / NH) & (SS - 1);
    int b = g / (NH * SS);
    int lo = g_qlo[b*SS + s], hi = g_qhi[b*SS + s];

    const float* qp = g_qkv + ((size_t)(b*SS + s))*(3*DD) + h*HDIM + lane*4;
    float4 qv = *(const float4*)qp;
    const float scale = 0.088388347648318440550f;   // 1/sqrt(128)

    const float* kbase = g_qkv + ((size_t)(b*SS))*(3*DD) + DD + h*HDIM + lane*4;
    float mx = -3.402823e38f;
    for (int k = lo; k < hi; k++) {
        float4 kv = *(const float4*)(kbase + (size_t)k*(3*DD));
        float d = qv.x*kv.x + qv.y*kv.y + qv.z*kv.z + qv.w*kv.w;
        #pragma unroll
        for (int o = 16; o > 0; o >>= 1) d += __shfl_xor_sync(0xffffffffu, d, o);
        d *= scale;
        if (lane == 0) dots[w][k - lo] = d;
        mx = fmaxf(mx, d);
    }
    __syncwarp();

    const float* vbase = g_qkv + ((size_t)(b*SS))*(3*DD) + 2*DD + h*HDIM + lane*4;
    float4 acc = make_float4(0.f, 0.f, 0.f, 0.f);
    float sum = 0.f;
    for (int k = lo; k < hi; k++) {
        float e = expf(dots[w][k - lo] - mx);
        sum += e;
        float4 vv = *(const float4*)(vbase + (size_t)k*(3*DD));
        acc.x += e*vv.x; acc.y += e*vv.y; acc.z += e*vv.z; acc.w += e*vv.w;
    }
    float inv = 1.0f / sum;
    float c0 = acc.x*inv, c1 = acc.y*inv, c2 = acc.z*inv, c3 = acc.w*inv;

    __half* d = g_ctx2 + ((size_t)(b*SS + s))*(2*DD) + h*HDIM + lane*4;
    __half h0 = __float2half_rn(c0), h1 = __float2half_rn(c1);
    __half h2 = __float2half_rn(c2), h3 = __float2half_rn(c3);
    *(__half2*)(d)     = __halves2half2(h0, h1);
    *(__half2*)(d + 2) = __halves2half2(h2, h3);
    __half l0 = __float2half_rn(c0 - __half2float(h0));
    __half l1 = __float2half_rn(c1 - __half2float(h1));
    __half l2 = __float2half_rn(c2 - __half2float(h2));
    __half l3 = __float2half_rn(c3 - __half2float(h3));
    *(__half2*)(d + DD)     = __halves2half2(l0, l1);
    *(__half2*)(d + DD + 2) = __halves2half2(l2, l3);
}

// pooling + embeddings, writes 2-way fp16 split chunk directly
__global__ void chunk_k(const float* __restrict__ size_emb,
                        const float* __restrict__ pos_enc) {
    int m = blockIdx.x, b = blockIdx.y;
    int cnt = g_segcount[b*MAXC + m];
    int st  = g_segstart[b*MAXC + m];
    __half* drow = g_chunk2 + ((size_t)b*MAXC + m) * (2*DD);
    for (int d = threadIdx.x; d < DD; d += 256) {
        float v;
        if (cnt > 0) {
            float sum = 0.f;
            for (int s = st; s < st + cnt; s++)
                sum += g_attnout[((size_t)b*SS + s)*DD + d];
            int cl = min(cnt, 1023);
            v = sum / (float)cnt + size_emb[(size_t)cl*DD + d];
        } else v = 0.f;
        v += pos_enc[(size_t)m*DD + d];
        __half h = __float2half_rn(v);
        drow[d]      = h;
        drow[DD + d] = __float2half_rn(v - __half2float(h));
    }
}

__global__ void ln_k(const float* __restrict__ gamma,
                     const float* __restrict__ beta,
                     float* __restrict__ out) {
    int r = blockIdx.x;
    const float* y = g_y + (size_t)r*DD;
    __shared__ float sh[256];
    float s = 0.f;
    for (int d = threadIdx.x; d < DD; d += 256) s += y[d];
    sh[threadIdx.x] = s; __syncthreads();
    for (int o = 128; o > 0; o >>= 1) {
        if (threadIdx.x < o) sh[threadIdx.x] += sh[threadIdx.x+o];
        __syncthreads();
    }
    float mu = sh[0] / (float)DD; __syncthreads();
    float v2 = 0.f;
    for (int d = threadIdx.x; d < DD; d += 256) { float t = y[d]-mu; v2 += t*t; }
    sh[threadIdx.x] = v2; __syncthreads();
    for (int o = 128; o > 0; o >>= 1) {
        if (threadIdx.x < o) sh[threadIdx.x] += sh[threadIdx.x+o];
        __syncthreads();
    }
    float inv = 1.0f / sqrtf(sh[0] / (float)DD + 1e-5f);
    for (int d = threadIdx.x; d < DD; d += 256)
        out[(size_t)r*DD + d] = (y[d] - mu) * inv * gamma[d] + beta[d];
}

// ---------------- host launchers ----------------
struct GemmArgs {
    const __half *A, *B;
    const float* bias;
    float* C;
    __half* C2;
    int M, N, K, lda, ldb, ldc, segoff;
    float oscale;
    long long sAi, sAo, sBi, sBo, sCi, sCo, sbias;
    int innerN, batch;
};

template<int ACT, int OMODE>
static void tg_launch(const GemmArgs& a) {
    dim3 grid(a.N/128, (a.M + 127)/128, a.batch);
    tgemm_k<ACT,OMODE><<<grid,256,TG_SMEM>>>(a.A, a.B, a.bias, a.C, a.C2,
        a.M, a.K, a.lda, a.ldb, a.ldc, a.segoff, a.oscale,
        a.sAi, a.sAo, a.sBi, a.sBo, a.sCi, a.sCo, a.sbias, a.innerN);
}

static void split2(const float* src, __half* dst, long long rows, int cols, float scale) {
    long long total = rows * cols;
    split2_k<<<(unsigned)((total + 255)/256), 256>>>(src, dst, total, cols, scale);
}

extern "C" void kernel_launch(void* const* d_in, const int* in_sizes, int n_in,
                              void* d_out, int out_size) {
    const float* x         = (const float*)d_in[0];
    const float* Wp        = (const float*)d_in[1];
    const float* bp        = (const float*)d_in[2];
    const float* detW1     = (const float*)d_in[3];
    const float* detb1     = (const float*)d_in[4];
    const float* detW2     = (const float*)d_in[5];
    const float* detb2     = (const float*)d_in[6];
    const float* detW3     = (const float*)d_in[7];
    const float* detb3     = (const float*)d_in[8];
    const float* in_proj_w = (const float*)d_in[9];
    const float* in_proj_b = (const float*)d_in[10];
    const float* out_w     = (const float*)d_in[11];
    const float* out_b     = (const float*)d_in[12];
    const float* size_emb  = (const float*)d_in[13];
    const float* pos_enc   = (const float*)d_in[14];
    const float* procW1    = (const float*)d_in[15];
    const float* procb1    = (const float*)d_in[16];
    const float* procW2    = (const float*)d_in[17];
    const float* procb2    = (const float*)d_in[18];
    const float* ln_g      = (const float*)d_in[19];
    const float* ln_b      = (const float*)d_in[20];
    float* outp = (float*)d_out;

    cudaFuncSetAttribute(tgemm_k<0,0>, cudaFuncAttributeMaxDynamicSharedMemorySize, TG_SMEM);
    cudaFuncSetAttribute(tgemm_k<1,0>, cudaFuncAttributeMaxDynamicSharedMemorySize, TG_SMEM);
    cudaFuncSetAttribute(tgemm_k<1,1>, cudaFuncAttributeMaxDynamicSharedMemorySize, TG_SMEM);
    cudaFuncSetAttribute(tgemm_k<0,1>, cudaFuncAttributeMaxDynamicSharedMemorySize, TG_SMEM);

    void *p;
    cudaGetSymbolAddress(&p, g_xling);   float* xling   = (float*)p;
    cudaGetSymbolAddress(&p, g_h2);      float* h2      = (float*)p;
    cudaGetSymbolAddress(&p, g_qkv);     float* qkv     = (float*)p;
    cudaGetSymbolAddress(&p, g_attnout); float* attnout = (float*)p;
    cudaGetSymbolAddress(&p, g_y);       float* yb      = (float*)p;
    cudaGetSymbolAddress(&p, g_x2);      __half* x2     = (__half*)p;
    cudaGetSymbolAddress(&p, g_Wp2);     __half* Wp2    = (__half*)p;
    cudaGetSymbolAddress(&p, g_bi2);     __half* bi2    = (__half*)p;
    cudaGetSymbolAddress(&p, g_dW1_2);   __half* dW1_2  = (__half*)p;
    cudaGetSymbolAddress(&p, g_h1_2);    __half* h1_2   = (__half*)p;
    cudaGetSymbolAddress(&p, g_dW2_2);   __half* dW2_2  = (__half*)p;
    cudaGetSymbolAddress(&p, g_wqkv2);   __half* wqkv2  = (__half*)p;
    cudaGetSymbolAddress(&p, g_ctx2);    __half* ctx2   = (__half*)p;
    cudaGetSymbolAddress(&p, g_outw2);   __half* outw2  = (__half*)p;
    cudaGetSymbolAddress(&p, g_chunk2);  __half* chunk2 = (__half*)p;
    cudaGetSymbolAddress(&p, g_pw1_2);   __half* pw1_2  = (__half*)p;
    cudaGetSymbolAddress(&p, g_hproc2);  __half* hproc2 = (__half*)p;
    cudaGetSymbolAddress(&p, g_pw2_2);   __half* pw2_2  = (__half*)p;

    // ===== input splits (weights scaled by 64 to keep fp16 lo plane normal) =====
    split2(x, x2, NB*SS, DD, 1.0f);
    split2(Wp, Wp2, DD, DD, WSCALE);
    split2(detW1, dW1_2, 3*DD, 2*DD, WSCALE);
    split2(detW2, dW2_2, 3*(DD/2), DD, WSCALE);
    split2(in_proj_w, wqkv2, 3*DD, DD, WSCALE);
    split2(out_w, outw2, DD, DD, WSCALE);
    split2(procW1, pw1_2, 2*DD, DD, WSCALE);
    split2(procW2, pw2_2, DD, 2*DD, WSCALE);
    {
        long long total8 = (long long)ROWS_DET * (2*2*DD) / 8;
        bi2_k<<<(unsigned)((total8 + 255)/256), 256>>>();
    }

    // ===== boundary path (fp16 3-product ~ fp32 accuracy) =====
    { GemmArgs a = { x2, Wp2, bp, xling, nullptr, NB*SS, DD, DD, 2*DD, 2*DD, DD, 0,
                     OSINV, 0,0,0,0,0,0,0, 1, 1 };
      tg_launch<0,0>(a); }
    norm_k<<<NB*SS, 256>>>();
    cos_k<<<dim3(CS_TOT, NB), 256>>>();
    base_k<<<(NB*SM1 + 255)/256, 256>>>();
    // h1 = gelu(bi @ detW1[n]^T + b) -> 2-way split directly
    { GemmArgs a = { bi2, dW1_2, detb1, nullptr, h1_2, ROWS_DET, DD, 2*DD,
                     2*2*DD, 2*2*DD, 2*DD, DD, OSINV,
                     0, 0, (long long)DD*2*2*DD, 0,
                     (long long)ROWS_DET*2*DD, 0, DD, 3, 3 };
      tg_launch<1,1>(a); }
    // h2 = gelu(h1 @ detW2[n]^T + b) fp32
    { GemmArgs a = { h1_2, dW2_2, detb2, h2, nullptr, ROWS_DET, DD/2, DD,
                     2*DD, 2*DD, DD/2, 0, OSINV,
                     (long long)ROWS_DET*2*DD, 0, (long long)(DD/2)*2*DD, 0,
                     (long long)ROWS_DET*(DD/2), 0, DD/2, 3, 3 };
      tg_launch<1,0>(a); }
    learned_final_k<<<ROWS_DET, 256>>>(detW3, detb3);
    seg_k<<<1, NB>>>();

    // ===== continuous path =====
    { GemmArgs a = { x2, wqkv2, in_proj_b, qkv, nullptr, NB*SS, 3*DD, DD,
                     2*DD, 2*DD, 3*DD, 0, OSINV, 0,0,0,0,0,0,0, 1, 1 };
      tg_launch<0,0>(a); }
    // fused segment attention (fp32) -> ctx2 (fp16 split)
    seg_attn_k<<<NB*SS*NH/8, 256>>>();
    // attn_out = ctx @ out_w^T + out_b
    { GemmArgs a = { ctx2, outw2, out_b, attnout, nullptr, NB*SS, DD, DD,
                     2*DD, 2*DD, DD, 0, OSINV, 0,0,0,0,0,0,0, 1, 1 };
      tg_launch<0,0>(a); }
    chunk_k<<<dim3(MAXC, NB), 256>>>(size_emb, pos_enc);
    // hproc = gelu(chunk @ procW1^T + b) -> 2-way split directly
    { GemmArgs a = { chunk2, pw1_2, procb1, nullptr, hproc2, NB*MAXC, 2*DD, DD,
                     2*DD, 2*DD, 2*2*DD, 2*DD, OSINV, 0,0,0,0,0,0,0, 1, 1 };
      tg_launch<1,1>(a); }
    // y = hproc @ procW2^T + b
    { GemmArgs a = { hproc2, pw2_2, procb2, yb, nullptr, NB*MAXC, DD, 2*DD,
                     2*2*DD, 2*2*DD, DD, 0, OSINV, 0,0,0,0,0,0,0, 1, 1 };
      tg_launch<0,0>(a); }
    ln_k<<<NB*MAXC, 256>>>(ln_g, ln_b, outp);
}

// round 8
// speedup vs baseline: 1.8568x; 1.0157x over previous
#include <cuda_runtime.h>
#include <cuda_fp16.h>
#include <math.h>
#include <stdint.h>

// ---------------- problem constants ----------------
#define NB 4
#define SS 1024
#define DD 1536
#define NH 12
#define HDIM 128
#define MAXC 256
#define SM1 1023
#define ROWS_DET (NB*SM1)        // 4092
#define CS_TOT (1023+511+255)    // 1789

#define WSCALE 64.0f
#define OSINV  0.015625f         // 1/64

// ---------------- fp32 scratch ----------------
__device__ float g_xling[(size_t)NB*SS*DD];
__device__ float g_norm[NB*SS];
__device__ float g_cs[NB*CS_TOT];
__device__ float g_base[NB*SM1];
__device__ float g_h2[(size_t)3*ROWS_DET*(DD/2)];
__device__ float g_final[NB*SM1];
__device__ int   g_seg[NB*SS];
__device__ int   g_qlo[NB*SS];
__device__ int   g_qhi[NB*SS];
__device__ int   g_segstart[NB*MAXC];
__device__ int   g_segcount[NB*MAXC];
__device__ float g_qkv[(size_t)NB*SS*3*DD];
__device__ float g_attnout[(size_t)NB*SS*DD];
__device__ float g_y[(size_t)NB*MAXC*DD];

// ---------------- fp16 2-way split scratch [rows][2K] (hi|lo) ----------------
__device__ __half g_x2[(size_t)NB*SS*2*DD];
__device__ __half g_Wp2[(size_t)DD*2*DD];
__device__ __half g_dW1_2[(size_t)3*DD*2*(2*DD)];
__device__ __half g_h1_2[(size_t)3*ROWS_DET*2*DD];
__device__ __half g_dW2_2[(size_t)3*(DD/2)*2*DD];
__device__ __half g_wqkv2[(size_t)3*DD*2*DD];
__device__ __half g_ctx2[(size_t)NB*SS*2*DD];
__device__ __half g_outw2[(size_t)DD*2*DD];
__device__ __half g_chunk2[(size_t)NB*MAXC*2*DD];
__device__ __half g_pw1_2[(size_t)2*DD*2*DD];
__device__ __half g_hproc2[(size_t)NB*MAXC*2*2*DD];
__device__ __half g_pw2_2[(size_t)DD*2*2*DD];

__device__ __forceinline__ float gelu_exact(float v) {
    return 0.5f * v * (1.0f + erff(v * 0.70710678118654752440f));
}
__device__ __forceinline__ uint32_t smem_u32(const void* p) {
    uint32_t a;
    asm("{ .reg .u64 t; cvta.to.shared.u64 t, %1; cvt.u32.u64 %0, t; }" : "=r"(a) : "l"(p));
    return a;
}

#define LDSM4(r0,r1,r2,r3,addr) \
    asm volatile("ldmatrix.sync.aligned.m8n8.x4.shared.b16 {%0,%1,%2,%3}, [%4];" \
        : "=r"(r0), "=r"(r1), "=r"(r2), "=r"(r3) : "r"(addr))

#define MMA16816(d, a, b0, b1) \
    asm volatile("mma.sync.aligned.m16n8k16.row.col.f32.f16.f16.f32 " \
        "{%0,%1,%2,%3},{%4,%5,%6,%7},{%8,%9},{%0,%1,%2,%3};" \
        : "+f"((d)[0]), "+f"((d)[1]), "+f"((d)[2]), "+f"((d)[3]) \
        : "r"((a)[0]), "r"((a)[1]), "r"((a)[2]), "r"((a)[3]), "r"(b0), "r"(b1))

#define CP_ASYNC16(dst, src, sz) \
    asm volatile("cp.async.ca.shared.global [%0], [%1], 16, %2;" :: "r"(dst), "l"(src), "r"(sz))
#define CP_COMMIT() asm volatile("cp.async.commit_group;" ::: "memory")
#define CP_WAIT1() asm volatile("cp.async.wait_group 1;" ::: "memory")
#define CP_WAIT0() asm volatile("cp.async.wait_group 0;" ::: "memory")

// ================= mma.sync fp16 split GEMM (2-stage, 2 CTAs/SM) =================
// A[M][2K] (hi|lo), B[N][2K] (hi|lo).  C = oscale * (Ah.Bh + Ah.Bl + Al.Bh) + bias
// BIG=1: A is g_x2 and rows are bigrams (b,s): chunk side selects x_s / x_{s+1}.
#define RSTRIDE 144
#define ATILE (128*RSTRIDE)        // 18432
#define BUFSZ (2*ATILE)            // 36864
#define TG_SMEM (2*BUFSZ)          // 73728

template<int ACT, int OMODE, int BIG>
__global__ void __launch_bounds__(256)
tgemm_k(const __half* __restrict__ A, const __half* __restrict__ B,
        const float* __restrict__ bias, float* __restrict__ C, __half* __restrict__ C2,
        int M, int K, int lda, int ldb, int ldc, int segoff, float oscale,
        long long sAi, long long sAo, long long sBi, long long sBo,
        long long sCi, long long sCo, long long sbias, int innerN)
{
    const int segA_[3] = {0,0,1};
    const int segB_[3] = {0,1,0};
    extern __shared__ char smem[];
    uint32_t sb = smem_u32(smem);
    int tid = threadIdx.x;
    int z = blockIdx.z, zi = z % innerN, zo = z / innerN;
    if (!BIG) A += (size_t)(zi*sAi + zo*sAo);
    B += (size_t)(zi*sBi + zo*sBo);
    if (OMODE == 0) C  += (size_t)(zi*sCi + zo*sCo);
    else            C2 += (size_t)(zi*sCi + zo*sCo);
    int m0 = blockIdx.y * 128, n0 = blockIdx.x * 128;

    const int KPC = K >> 6;
    const int NC = 3 * KPC;

    // per-thread A-load slots (row/col fixed across chunks)
    int arow_[4]; uint32_t asz_[4]; long long aoff_[4]; int ac_[4];
    #pragma unroll
    for (int i = 0; i < 4; i++) {
        int f = tid + (i << 8);
        int row = f >> 3, c = f & 7;
        int gr = m0 + row;
        int grc = gr < M ? gr : (M - 1);
        arow_[i] = row; ac_[i] = c;
        asz_[i] = gr < M ? 16u : 0u;
        if (BIG) {
            int b = grc / SM1, s = grc % SM1;
            aoff_[i] = (long long)(b*SS + s) * (2*DD);
        } else {
            aoff_[i] = (long long)grc * lda;
        }
    }

    auto issue = [&](int kc, int buf) {
        int p = kc / KPC;
        int k0 = (kc - p * KPC) << 6;
        uint32_t sA = sb + buf * BUFSZ;
        uint32_t sB = sA + ATILE;
        if (BIG) {
            int side = (k0 >= DD) ? 1 : 0;
            long long cofs = (long long)side*(2*DD) + segA_[p]*DD + (k0 - side*DD);
            #pragma unroll
            for (int i = 0; i < 4; i++) {
                const void* src = A + aoff_[i] + cofs + ac_[i] * 8;
                CP_ASYNC16(sA + arow_[i] * RSTRIDE + ac_[i] * 16, src, asz_[i]);
            }
        } else {
            const __half* Ap = A + (size_t)segA_[p] * K + k0;
            #pragma unroll
            for (int i = 0; i < 4; i++) {
                const void* src = Ap + aoff_[i] + ac_[i] * 8;
                CP_ASYNC16(sA + arow_[i] * RSTRIDE + ac_[i] * 16, src, asz_[i]);
            }
        }
        const __half* Bp = B + (size_t)segB_[p] * K + k0;
        #pragma unroll
        for (int i = 0; i < 4; i++) {
            int f = tid + (i << 8);
            int row = f >> 3, c = f & 7;
            const void* src = Bp + (size_t)(n0 + row) * ldb + c * 8;
            CP_ASYNC16(sB + row * RSTRIDE + c * 16, src, 16u);
        }
    };

    int lane = tid & 31, w = tid >> 5;
    int wm = w & 1, wn = w >> 1;
    uint32_t a_row = ((lane >> 3) & 1) * 8 + (lane & 7);
    uint32_t a_cs  = lane >> 4;
    uint32_t b_row = (lane >> 4) * 8 + (lane & 7);
    uint32_t b_cs  = (lane >> 3) & 1;

    float acc[4][4][4];
    #pragma unroll
    for (int i = 0; i < 4; i++)
        #pragma unroll
        for (int j = 0; j < 4; j++)
            #pragma unroll
            for (int r = 0; r < 4; r++) acc[i][j][r] = 0.f;

    issue(0, 0);
    CP_COMMIT();

    for (int kc = 0; kc < NC; kc++) {
        int cur = kc & 1;
        if (kc + 1 < NC) { issue(kc + 1, cur ^ 1); CP_COMMIT(); CP_WAIT1(); }
        else             { CP_WAIT0(); }
        __syncthreads();

        uint32_t sA = sb + cur * BUFSZ;
        uint32_t sB = sA + ATILE;
        #pragma unroll
        for (int ks = 0; ks < 4; ks++) {
            uint32_t av[4][4], bv[2][4];
            #pragma unroll
            for (int mt = 0; mt < 4; mt++) {
                uint32_t ad = sA + (wm*64 + mt*16 + a_row) * RSTRIDE + ((ks*2 + a_cs) << 4);
                LDSM4(av[mt][0], av[mt][1], av[mt][2], av[mt][3], ad);
            }
            #pragma unroll
            for (int bt = 0; bt < 2; bt++) {
                uint32_t bd = sB + (wn*32 + bt*16 + b_row) * RSTRIDE + ((ks*2 + b_cs) << 4);
                LDSM4(bv[bt][0], bv[bt][1], bv[bt][2], bv[bt][3], bd);
            }
            #pragma unroll
            for (int mt = 0; mt < 4; mt++)
                #pragma unroll
                for (int nt = 0; nt < 4; nt++) {
                    uint32_t b0 = bv[nt >> 1][(nt & 1) * 2];
                    uint32_t b1 = bv[nt >> 1][(nt & 1) * 2 + 1];
                    MMA16816(acc[mt][nt], av[mt], b0, b1);
                }
        }
        __syncthreads();
    }

    // ---- epilogue ----
    if (bias) bias += (size_t)z * (size_t)sbias;
    #pragma unroll
    for (int mt = 0; mt < 4; mt++) {
        int r0 = m0 + wm*64 + mt*16 + (lane >> 2);
        #pragma unroll
        for (int nt = 0; nt < 4; nt++) {
            int col = n0 + wn*32 + nt*8 + (lane & 3)*2;
            float bb0 = 0.f, bb1 = 0.f;
            if (bias) { bb0 = bias[col]; bb1 = bias[col+1]; }
            #pragma unroll
            for (int half_ = 0; half_ < 2; half_++) {
                int r = r0 + half_*8;
                if (r >= M) continue;
                float v0 = acc[mt][nt][half_*2]   * oscale + bb0;
                float v1 = acc[mt][nt][half_*2+1] * oscale + bb1;
                if (ACT == 1) { v0 = gelu_exact(v0); v1 = gelu_exact(v1); }
                if (OMODE == 0) {
                    *(float2*)(C + (size_t)r*ldc + col) = make_float2(v0, v1);
                } else {
                    __half* d = C2 + (size_t)r*ldc + col;
                    __half h0 = __float2half_rn(v0);
                    __half h1 = __float2half_rn(v1);
                    __half l0 = __float2half_rn(v0 - __half2float(h0));
                    __half l1 = __float2half_rn(v1 - __half2float(h1));
                    *(__half2*)(d)          = __halves2half2(h0, h1);
                    *(__half2*)(d + segoff) = __halves2half2(l0, l1);
                }
            }
        }
    }
}

// ================= split kernel =================
__global__ void split2_k(const float* __restrict__ src, __half* __restrict__ dst,
                         long long total, int C, float scale) {
    long long idx = (long long)blockIdx.x * 256 + threadIdx.x;
    if (idx >= total) return;
    long long r = idx / C; int c = (int)(idx % C);
    float v = src[idx] * scale;
    __half h = __float2half_rn(v);
    __half l = __float2half_rn(v - __half2float(h));
    __half* d = dst + r * (2LL*C) + c;
    d[0] = h; d[C] = l;
}

// ---------------- small kernels ----------------
__global__ void norm_k() {
    int r = blockIdx.x;
    const float* p = g_xling + (size_t)r * DD;
    float ss = 0.f;
    for (int i = threadIdx.x; i < DD; i += 256) { float v = p[i]; ss += v*v; }
    __shared__ float sh[256];
    sh[threadIdx.x] = ss; __syncthreads();
    for (int o = 128; o > 0; o >>= 1) {
        if (threadIdx.x < o) sh[threadIdx.x] += sh[threadIdx.x + o];
        __syncthreads();
    }
    if (threadIdx.x == 0) g_norm[r] = fmaxf(sqrtf(sh[0]), 1e-8f);
}

__global__ void cos_k() {
    int b = blockIdx.y, t = blockIdx.x;
    int scale, i;
    if (t < 1023)      { scale = 1; i = t; }
    else if (t < 1534) { scale = 2; i = t - 1023; }
    else               { scale = 4; i = t - 1534; }
    int s0 = i * scale, s1 = s0 + scale;
    const float* a = g_xling + ((size_t)b*SS + s0) * DD;
    const float* c = g_xling + ((size_t)b*SS + s1) * DD;
    float d = 0.f;
    for (int j = threadIdx.x; j < DD; j += 256) d += a[j] * c[j];
    __shared__ float sh[256];
    sh[threadIdx.x] = d; __syncthreads();
    for (int o = 128; o > 0; o >>= 1) {
        if (threadIdx.x < o) sh[threadIdx.x] += sh[threadIdx.x + o];
        __syncthreads();
    }
    if (threadIdx.x == 0)
        g_cs[b*CS_TOT + t] = sh[0] / (g_norm[b*SS + s0] * g_norm[b*SS + s1]);
}

__global__ void base_k() {
    int idx = blockIdx.x * 256 + threadIdx.x;
    if (idx >= NB*SM1) return;
    int b = idx / SM1, j = idx % SM1;
    const int Ls[3]   = {1023, 511, 255};
    const int offs[3] = {0, 1023, 1534};
    float acc = 0.f;
    #pragma unroll
    for (int u = 0; u < 3; u++) {
        int L = Ls[u];
        float ratio = (float)((double)L / 1023.0);
        float src = ((float)j + 0.5f) * ratio - 0.5f;
        src = fminf(fmaxf(src, 0.0f), (float)(L - 1));
        int i0 = (int)floorf(src);
        int i1 = min(i0 + 1, L - 1);
        float w = src - (float)i0;
        const float* cs = g_cs + b*CS_TOT + offs[u];
        acc += cs[i0] * (1.0f - w) + cs[i1] * w;
    }
    g_base[idx] = 0.5f * (1.0f - acc / 3.0f);
}

__global__ void learned_final_k(const float* __restrict__ detW3,
                                const float* __restrict__ detb3) {
    int r = blockIdx.x;
    __shared__ float sh[256];
    __shared__ float sacc;
    if (threadIdx.x == 0) sacc = 0.f;
    for (int n = 0; n < 3; n++) {
        const float* h2p = g_h2 + ((size_t)n*ROWS_DET + r) * (DD/2);
        const float* w   = detW3 + n*(DD/2);
        float part = 0.f;
        for (int j = threadIdx.x; j < DD/2; j += 256) part += h2p[j] * w[j];
        __syncthreads();
        sh[threadIdx.x] = part; __syncthreads();
        for (int o = 128; o > 0; o >>= 1) {
            if (threadIdx.x < o) sh[threadIdx.x] += sh[threadIdx.x + o];
            __syncthreads();
        }
        if (threadIdx.x == 0) {
            float t = sh[0] + detb3[n];
            sacc += 1.0f / (1.0f + expf(-t));
        }
        __syncthreads();
    }
    if (threadIdx.x == 0)
        g_final[r] = 0.6f * g_base[r] + 0.4f * (sacc / 3.0f);
}

// parallel segmentation: integer scans (exact, order-independent)
__global__ void __launch_bounds__(SS)
seg_scan_k() {
    int b = blockIdx.x, t = threadIdx.x;
    __shared__ int sscan[SS];
    __shared__ int smax[SS];
    __shared__ int rmin[SS];
    float bv = (t == 0) ? 1.0f : g_final[b*SM1 + t - 1];
    int f = (t == 0) ? 1 : (bv > 0.5f ? 1 : 0);
    sscan[t] = f;
    smax[t]  = f ? t : -1;
    rmin[t]  = f ? t : SS;
    __syncthreads();
    for (int o = 1; o < SS; o <<= 1) {
        int vs = sscan[t];
        int vm = smax[t];
        int vr = rmin[t];
        int vs2 = (t >= o) ? sscan[t - o] : 0;
        int vm2 = (t >= o) ? smax[t - o]  : -1;
        int vr2 = (t + o < SS) ? rmin[t + o] : SS;
        __syncthreads();
        sscan[t] = vs + vs2;
        smax[t]  = max(vm, vm2);
        rmin[t]  = min(vr, vr2);
        __syncthreads();
    }
    int m = sscan[t] - 1;
    g_seg[b*SS + t] = m;
    g_qlo[b*SS + t] = smax[t];
    int hi = (t < SS - 1) ? rmin[t + 1] : SS;
    g_qhi[b*SS + t] = hi;
    if (t < MAXC) { g_segstart[b*MAXC + t] = 0; g_segcount[b*MAXC + t] = 0; }
    __syncthreads();
    if (f && m < MAXC) {
        g_segstart[b*MAXC + m] = t;
        g_segcount[b*MAXC + m] = hi - t;
    }
}

// fused segment attention: one warp per (b, s, h); fp32; writes fp16-split ctx
__global__ void __launch_bounds__(256)
seg_attn_k() {
    __shared__ float dots[8][SS];
    int w = threadIdx.x >> 5, lane = threadIdx.x & 31;
    int g = blockIdx.x * 8 + w;
    int h = g % NH;
    int s = (g / NH) & (SS - 1);
    int b = g / (NH * SS);
    int lo = g_qlo[b*SS + s], hi = g_qhi[b*SS + s];

    const float* qp = g_qkv + ((size_t)(b*SS + s))*(3*DD) + h*HDIM + lane*4;
    float4 qv = *(const float4*)qp;
    const float scale = 0.088388347648318440550f;   // 1/sqrt(128)

    const float* kbase = g_qkv + ((size_t)(b*SS))*(3*DD) + DD + h*HDIM + lane*4;
    float mx = -3.402823e38f;
    for (int k = lo; k < hi; k++) {
        float4 kv = *(const float4*)(kbase + (size_t)k*(3*DD));
        float d = qv.x*kv.x + qv.y*kv.y + qv.z*kv.z + qv.w*kv.w;
        #pragma unroll
        for (int o = 16; o > 0; o >>= 1) d += __shfl_xor_sync(0xffffffffu, d, o);
        d *= scale;
        if (lane == 0) dots[w][k - lo] = d;
        mx = fmaxf(mx, d);
    }
    __syncwarp();

    const float* vbase = g_qkv + ((size_t)(b*SS))*(3*DD) + 2*DD + h*HDIM + lane*4;
    float4 acc = make_float4(0.f, 0.f, 0.f, 0.f);
    float sum = 0.f;
    for (int k = lo; k < hi; k++) {
        float e = expf(dots[w][k - lo] - mx);
        sum += e;
        float4 vv = *(const float4*)(vbase + (size_t)k*(3*DD));
        acc.x += e*vv.x; acc.y += e*vv.y; acc.z += e*vv.z; acc.w += e*vv.w;
    }
    float inv = 1.0f / sum;
    float c0 = acc.x*inv, c1 = acc.y*inv, c2 = acc.z*inv, c3 = acc.w*inv;

    __half* d = g_ctx2 + ((size_t)(b*SS + s))*(2*DD) + h*HDIM + lane*4;
    __half h0 = __float2half_rn(c0), h1 = __float2half_rn(c1);
    __half h2 = __float2half_rn(c2), h3 = __float2half_rn(c3);
    *(__half2*)(d)     = __halves2half2(h0, h1);
    *(__half2*)(d + 2) = __halves2half2(h2, h3);
    __half l0 = __float2half_rn(c0 - __half2float(h0));
    __half l1 = __float2half_rn(c1 - __half2float(h1));
    __half l2 = __float2half_rn(c2 - __half2float(h2));
    __half l3 = __float2half_rn(c3 - __half2float(h3));
    *(__half2*)(d + DD)     = __halves2half2(l0, l1);
    *(__half2*)(d + DD + 2) = __halves2half2(l2, l3);
}

// pooling + embeddings, writes 2-way fp16 split chunk directly
__global__ void chunk_k(const float* __restrict__ size_emb,
                        const float* __restrict__ pos_enc) {
    int m = blockIdx.x, b = blockIdx.y;
    int cnt = g_segcount[b*MAXC + m];
    int st  = g_segstart[b*MAXC + m];
    __half* drow = g_chunk2 + ((size_t)b*MAXC + m) * (2*DD);
    for (int d = threadIdx.x; d < DD; d += 256) {
        float v;
        if (cnt > 0) {
            float sum = 0.f;
            for (int s = st; s < st + cnt; s++)
                sum += g_attnout[((size_t)b*SS + s)*DD + d];
            int cl = min(cnt, 1023);
            v = sum / (float)cnt + size_emb[(size_t)cl*DD + d];
        } else v = 0.f;
        v += pos_enc[(size_t)m*DD + d];
        __half h = __float2half_rn(v);
        drow[d]      = h;
        drow[DD + d] = __float2half_rn(v - __half2float(h));
    }
}

__global__ void ln_k(const float* __restrict__ gamma,
                     const float* __restrict__ beta,
                     float* __restrict__ out) {
    int r = blockIdx.x;
    const float* y = g_y + (size_t)r*DD;
    __shared__ float sh[256];
    float s = 0.f;
    for (int d = threadIdx.x; d < DD; d += 256) s += y[d];
    sh[threadIdx.x] = s; __syncthreads();
    for (int o = 128; o > 0; o >>= 1) {
        if (threadIdx.x < o) sh[threadIdx.x] += sh[threadIdx.x+o];
        __syncthreads();
    }
    float mu = sh[0] / (float)DD; __syncthreads();
    float v2 = 0.f;
    for (int d = threadIdx.x; d < DD; d += 256) { float t = y[d]-mu; v2 += t*t; }
    sh[threadIdx.x] = v2; __syncthreads();
    for (int o = 128; o > 0; o >>= 1) {
        if (threadIdx.x < o) sh[threadIdx.x] += sh[threadIdx.x+o];
        __syncthreads();
    }
    float inv = 1.0f / sqrtf(sh[0] / (float)DD + 1e-5f);
    for (int d = threadIdx.x; d < DD; d += 256)
        out[(size_t)r*DD + d] = (y[d] - mu) * inv * gamma[d] + beta[d];
}

// ---------------- host launchers ----------------
struct GemmArgs {
    const __half *A, *B;
    const float* bias;
    float* C;
    __half* C2;
    int M, N, K, lda, ldb, ldc, segoff;
    float oscale;
    long long sAi, sAo, sBi, sBo, sCi, sCo, sbias;
    int innerN, batch;
};

template<int ACT, int OMODE, int BIG>
static void tg_launch(const GemmArgs& a) {
    dim3 grid(a.N/128, (a.M + 127)/128, a.batch);
    tgemm_k<ACT,OMODE,BIG><<<grid,256,TG_SMEM>>>(a.A, a.B, a.bias, a.C, a.C2,
        a.M, a.K, a.lda, a.ldb, a.ldc, a.segoff, a.oscale,
        a.sAi, a.sAo, a.sBi, a.sBo, a.sCi, a.sCo, a.sbias, a.innerN);
}

static void split2(const float* src, __half* dst, long long rows, int cols, float scale) {
    long long total = rows * cols;
    split2_k<<<(unsigned)((total + 255)/256), 256>>>(src, dst, total, cols, scale);
}

extern "C" void kernel_launch(void* const* d_in, const int* in_sizes, int n_in,
                              void* d_out, int out_size) {
    const float* x         = (const float*)d_in[0];
    const float* Wp        = (const float*)d_in[1];
    const float* bp        = (const float*)d_in[2];
    const float* detW1     = (const float*)d_in[3];
    const float* detb1     = (const float*)d_in[4];
    const float* detW2     = (const float*)d_in[5];
    const float* detb2     = (const float*)d_in[6];
    const float* detW3     = (const float*)d_in[7];
    const float* detb3     = (const float*)d_in[8];
    const float* in_proj_w = (const float*)d_in[9];
    const float* in_proj_b = (const float*)d_in[10];
    const float* out_w     = (const float*)d_in[11];
    const float* out_b     = (const float*)d_in[12];
    const float* size_emb  = (const float*)d_in[13];
    const float* pos_enc   = (const float*)d_in[14];
    const float* procW1    = (const float*)d_in[15];
    const float* procb1    = (const float*)d_in[16];
    const float* procW2    = (const float*)d_in[17];
    const float* procb2    = (const float*)d_in[18];
    const float* ln_g      = (const float*)d_in[19];
    const float* ln_b      = (const float*)d_in[20];
    float* outp = (float*)d_out;

    cudaFuncSetAttribute(tgemm_k<0,0,0>, cudaFuncAttributeMaxDynamicSharedMemorySize, TG_SMEM);
    cudaFuncSetAttribute(tgemm_k<1,0,0>, cudaFuncAttributeMaxDynamicSharedMemorySize, TG_SMEM);
    cudaFuncSetAttribute(tgemm_k<1,1,0>, cudaFuncAttributeMaxDynamicSharedMemorySize, TG_SMEM);
    cudaFuncSetAttribute(tgemm_k<1,1,1>, cudaFuncAttributeMaxDynamicSharedMemorySize, TG_SMEM);

    void *p;
    cudaGetSymbolAddress(&p, g_xling);   float* xling   = (float*)p;
    cudaGetSymbolAddress(&p, g_h2);      float* h2      = (float*)p;
    cudaGetSymbolAddress(&p, g_qkv);     float* qkv     = (float*)p;
    cudaGetSymbolAddress(&p, g_attnout); float* attnout = (float*)p;
    cudaGetSymbolAddress(&p, g_y);       float* yb      = (float*)p;
    cudaGetSymbolAddress(&p, g_x2);      __half* x2     = (__half*)p;
    cudaGetSymbolAddress(&p, g_Wp2);     __half* Wp2    = (__half*)p;
    cudaGetSymbolAddress(&p, g_dW1_2);   __half* dW1_2  = (__half*)p;
    cudaGetSymbolAddress(&p, g_h1_2);    __half* h1_2   = (__half*)p;
    cudaGetSymbolAddress(&p, g_dW2_2);   __half* dW2_2  = (__half*)p;
    cudaGetSymbolAddress(&p, g_wqkv2);   __half* wqkv2  = (__half*)p;
    cudaGetSymbolAddress(&p, g_ctx2);    __half* ctx2   = (__half*)p;
    cudaGetSymbolAddress(&p, g_outw2);   __half* outw2  = (__half*)p;
    cudaGetSymbolAddress(&p, g_chunk2);  __half* chunk2 = (__half*)p;
    cudaGetSymbolAddress(&p, g_pw1_2);   __half* pw1_2  = (__half*)p;
    cudaGetSymbolAddress(&p, g_hproc2);  __half* hproc2 = (__half*)p;
    cudaGetSymbolAddress(&p, g_pw2_2);   __half* pw2_2  = (__half*)p;

    // ===== input splits (weights scaled by 64 to keep fp16 lo plane normal) =====
    split2(x, x2, NB*SS, DD, 1.0f);
    split2(Wp, Wp2, DD, DD, WSCALE);
    split2(detW1, dW1_2, 3*DD, 2*DD, WSCALE);
    split2(detW2, dW2_2, 3*(DD/2), DD, WSCALE);
    split2(in_proj_w, wqkv2, 3*DD, DD, WSCALE);
    split2(out_w, outw2, DD, DD, WSCALE);
    split2(procW1, pw1_2, 2*DD, DD, WSCALE);
    split2(procW2, pw2_2, DD, 2*DD, WSCALE);

    // ===== boundary path (fp16 3-product ~ fp32 accuracy) =====
    { GemmArgs a = { x2, Wp2, bp, xling, nullptr, NB*SS, DD, DD, 2*DD, 2*DD, DD, 0,
                     OSINV, 0,0,0,0,0,0,0, 1, 1 };
      tg_launch<0,0,0>(a); }
    norm_k<<<NB*SS, 256>>>();
    cos_k<<<dim3(CS_TOT, NB), 256>>>();
    base_k<<<(NB*SM1 + 255)/256, 256>>>();
    // h1 = gelu(bi @ detW1[n]^T + b) -> 2-way split directly; A gathered from x2 (BIG=1)
    { GemmArgs a = { x2, dW1_2, detb1, nullptr, h1_2, ROWS_DET, DD, 2*DD,
                     2*DD, 2*2*DD, 2*DD, DD, OSINV,
                     0, 0, (long long)DD*2*2*DD, 0,
                     (long long)ROWS_DET*2*DD, 0, DD, 3, 3 };
      tg_launch<1,1,1>(a); }
    // h2 = gelu(h1 @ detW2[n]^T + b) fp32
    { GemmArgs a = { h1_2, dW2_2, detb2, h2, nullptr, ROWS_DET, DD/2, DD,
                     2*DD, 2*DD, DD/2, 0, OSINV,
                     (long long)ROWS_DET*2*DD, 0, (long long)(DD/2)*2*DD, 0,
                     (long long)ROWS_DET*(DD/2), 0, DD/2, 3, 3 };
      tg_launch<1,0,0>(a); }
    learned_final_k<<<ROWS_DET, 256>>>(detW3, detb3);
    seg_scan_k<<<NB, SS>>>();

    // ===== continuous path =====
    { GemmArgs a = { x2, wqkv2, in_proj_b, qkv, nullptr, NB*SS, 3*DD, DD,
                     2*DD, 2*DD, 3*DD, 0, OSINV, 0,0,0,0,0,0,0, 1, 1 };
      tg_launch<0,0,0>(a); }
    // fused segment attention (fp32) -> ctx2 (fp16 split)
    seg_attn_k<<<NB*SS*NH/8, 256>>>();
    // attn_out = ctx @ out_w^T + out_b
    { GemmArgs a = { ctx2, outw2, out_b, attnout, nullptr, NB*SS, DD, DD,
                     2*DD, 2*DD, DD, 0, OSINV, 0,0,0,0,0,0,0, 1, 1 };
      tg_launch<0,0,0>(a); }
    chunk_k<<<dim3(MAXC, NB), 256>>>(size_emb, pos_enc);
    // hproc = gelu(chunk @ procW1^T + b) -> 2-way split directly
    { GemmArgs a = { chunk2, pw1_2, procb1, nullptr, hproc2, NB*MAXC, 2*DD, DD,
                     2*DD, 2*DD, 2*2*DD, 2*DD, OSINV, 0,0,0,0,0,0,0, 1, 1 };
      tg_launch<1,1,0>(a); }
    // y = hproc @ procW2^T + b
    { GemmArgs a = { hproc2, pw2_2, procb2, yb, nullptr, NB*MAXC, DD, 2*DD,
                     2*2*DD, 2*2*DD, DD, 0, OSINV, 0,0,0,0,0,0,0, 1, 1 };
      tg_launch<0,0,0>(a); }
    ln_k<<<NB*MAXC, 256>>>(ln_g, ln_b, outp);
}

// round 9
// speedup vs baseline: 2.0215x; 1.0887x over previous
#include <cuda_runtime.h>
#include <cuda_fp16.h>
#include <math.h>
#include <stdint.h>

// ---------------- problem constants ----------------
#define NB 4
#define SS 1024
#define DD 1536
#define NH 12
#define HDIM 128
#define MAXC 256
#define SM1 1023
#define ROWS_DET (NB*SM1)        // 4092
#define CS_TOT (1023+511+255)    // 1789
#define XQ 6144                  // combined xling|qkv row width
#define QOFF 1536                // qkv column offset in combined buffer

#define WSCALE 64.0f
#define OSINV  0.015625f         // 1/64

// ---------------- fp32 scratch ----------------
__device__ float g_xq[(size_t)NB*SS*XQ];       // [.,0:1536)=xling, [.,1536:6144)=qkv
__device__ float g_bc[XQ];                     // combined bias
__device__ float g_norm[NB*SS];
__device__ float g_cs[NB*CS_TOT];
__device__ float g_base[NB*SM1];
__device__ float g_h2[(size_t)3*ROWS_DET*(DD/2)];
__device__ float g_final[NB*SM1];
__device__ int   g_seg[NB*SS];
__device__ int   g_qlo[NB*SS];
__device__ int   g_qhi[NB*SS];
__device__ int   g_segstart[NB*MAXC];
__device__ int   g_segcount[NB*MAXC];
__device__ float g_attnout[(size_t)NB*SS*DD];
__device__ float g_y[(size_t)NB*MAXC*DD];

// ---------------- fp16 2-way split scratch [rows][2K] (hi|lo) ----------------
__device__ __half g_x2[(size_t)NB*SS*2*DD];
__device__ __half g_wc2[(size_t)XQ*2*DD];      // combined [Wp | in_proj_w] split
__device__ __half g_dW1_2[(size_t)3*DD*2*(2*DD)];
__device__ __half g_h1_2[(size_t)3*ROWS_DET*2*DD];
__device__ __half g_dW2_2[(size_t)3*(DD/2)*2*DD];
__device__ __half g_ctx2[(size_t)NB*SS*2*DD];
__device__ __half g_outw2[(size_t)DD*2*DD];
__device__ __half g_chunk2[(size_t)NB*MAXC*2*DD];
__device__ __half g_pw1_2[(size_t)2*DD*2*DD];
__device__ __half g_hproc2[(size_t)NB*MAXC*2*2*DD];
__device__ __half g_pw2_2[(size_t)DD*2*2*DD];

__device__ __forceinline__ float gelu_exact(float v) {
    return 0.5f * v * (1.0f + erff(v * 0.70710678118654752440f));
}
__device__ __forceinline__ uint32_t smem_u32(const void* p) {
    uint32_t a;
    asm("{ .reg .u64 t; cvta.to.shared.u64 t, %1; cvt.u32.u64 %0, t; }" : "=r"(a) : "l"(p));
    return a;
}

#define LDSM4(r0,r1,r2,r3,addr) \
    asm volatile("ldmatrix.sync.aligned.m8n8.x4.shared.b16 {%0,%1,%2,%3}, [%4];" \
        : "=r"(r0), "=r"(r1), "=r"(r2), "=r"(r3) : "r"(addr))

#define MMA16816(d, a, b0, b1) \
    asm volatile("mma.sync.aligned.m16n8k16.row.col.f32.f16.f16.f32 " \
        "{%0,%1,%2,%3},{%4,%5,%6,%7},{%8,%9},{%0,%1,%2,%3};" \
        : "+f"((d)[0]), "+f"((d)[1]), "+f"((d)[2]), "+f"((d)[3]) \
        : "r"((a)[0]), "r"((a)[1]), "r"((a)[2]), "r"((a)[3]), "r"(b0), "r"(b1))

#define CP_ASYNC16(dst, src, sz) \
    asm volatile("cp.async.ca.shared.global [%0], [%1], 16, %2;" :: "r"(dst), "l"(src), "r"(sz))
#define CP_COMMIT() asm volatile("cp.async.commit_group;" ::: "memory")
#define CP_WAIT1() asm volatile("cp.async.wait_group 1;" ::: "memory")
#define CP_WAIT0() asm volatile("cp.async.wait_group 0;" ::: "memory")

// ================= mma.sync fp16 split GEMM (2-stage, 2 CTAs/SM) =================
// A[M][2K] (hi|lo), B[N][2K] (hi|lo).
// Product count per column tile: np = (n0 < splitN) ? npA : npB.
//   np=3: Ah.Bh + Ah.Bl + Al.Bh   (chunk order identical to round 8)
//   np=2: Ah.Bh + Ah.Bl           (weights full precision, data fp16-truncated)
// BIG=1: A is g_x2 and rows are bigrams (b,s): chunk side selects x_s / x_{s+1}.
#define RSTRIDE 144
#define ATILE (128*RSTRIDE)        // 18432
#define BUFSZ (2*ATILE)            // 36864
#define TG_SMEM (2*BUFSZ)          // 73728

template<int ACT, int OMODE, int BIG>
__global__ void __launch_bounds__(256)
tgemm_k(const __half* __restrict__ A, const __half* __restrict__ B,
        const float* __restrict__ bias, float* __restrict__ C, __half* __restrict__ C2,
        int M, int K, int lda, int ldb, int ldc, int segoff, float oscale,
        int npA, int npB, int splitN,
        long long sAi, long long sAo, long long sBi, long long sBo,
        long long sCi, long long sCo, long long sbias, int innerN)
{
    const int segA_[3] = {0,0,1};
    const int segB_[3] = {0,1,0};
    extern __shared__ char smem[];
    uint32_t sb = smem_u32(smem);
    int tid = threadIdx.x;
    int z = blockIdx.z, zi = z % innerN, zo = z / innerN;
    if (!BIG) A += (size_t)(zi*sAi + zo*sAo);
    B += (size_t)(zi*sBi + zo*sBo);
    if (OMODE == 0) C  += (size_t)(zi*sCi + zo*sCo);
    else            C2 += (size_t)(zi*sCi + zo*sCo);
    int m0 = blockIdx.y * 128, n0 = blockIdx.x * 128;

    const int KPC = K >> 6;
    const int NP = (n0 < splitN) ? npA : npB;
    const int NC = NP * KPC;

    // per-thread A-load slots (row/col fixed across chunks)
    int arow_[4]; uint32_t asz_[4]; long long aoff_[4]; int ac_[4];
    #pragma unroll
    for (int i = 0; i < 4; i++) {
        int f = tid + (i << 8);
        int row = f >> 3, c = f & 7;
        int gr = m0 + row;
        int grc = gr < M ? gr : (M - 1);
        arow_[i] = row; ac_[i] = c;
        asz_[i] = gr < M ? 16u : 0u;
        if (BIG) {
            int b = grc / SM1, s = grc % SM1;
            aoff_[i] = (long long)(b*SS + s) * (2*DD);
        } else {
            aoff_[i] = (long long)grc * lda;
        }
    }

    auto issue = [&](int kc, int buf) {
        int p = kc / KPC;
        int k0 = (kc - p * KPC) << 6;
        uint32_t sA = sb + buf * BUFSZ;
        uint32_t sB = sA + ATILE;
        if (BIG) {
            int side = (k0 >= DD) ? 1 : 0;
            long long cofs = (long long)side*(2*DD) + segA_[p]*DD + (k0 - side*DD);
            #pragma unroll
            for (int i = 0; i < 4; i++) {
                const void* src = A + aoff_[i] + cofs + ac_[i] * 8;
                CP_ASYNC16(sA + arow_[i] * RSTRIDE + ac_[i] * 16, src, asz_[i]);
            }
        } else {
            const __half* Ap = A + (size_t)segA_[p] * K + k0;
            #pragma unroll
            for (int i = 0; i < 4; i++) {
                const void* src = Ap + aoff_[i] + ac_[i] * 8;
                CP_ASYNC16(sA + arow_[i] * RSTRIDE + ac_[i] * 16, src, asz_[i]);
            }
        }
        const __half* Bp = B + (size_t)segB_[p] * K + k0;
        #pragma unroll
        for (int i = 0; i < 4; i++) {
            int f = tid + (i << 8);
            int row = f >> 3, c = f & 7;
            const void* src = Bp + (size_t)(n0 + row) * ldb + c * 8;
            CP_ASYNC16(sB + row * RSTRIDE + c * 16, src, 16u);
        }
    };

    int lane = tid & 31, w = tid >> 5;
    int wm = w & 1, wn = w >> 1;
    uint32_t a_row = ((lane >> 3) & 1) * 8 + (lane & 7);
    uint32_t a_cs  = lane >> 4;
    uint32_t b_row = (lane >> 4) * 8 + (lane & 7);
    uint32_t b_cs  = (lane >> 3) & 1;

    float acc[4][4][4];
    #pragma unroll
    for (int i = 0; i < 4; i++)
        #pragma unroll
        for (int j = 0; j < 4; j++)
            #pragma unroll
            for (int r = 0; r < 4; r++) acc[i][j][r] = 0.f;

    issue(0, 0);
    CP_COMMIT();

    for (int kc = 0; kc < NC; kc++) {
        int cur = kc & 1;
        if (kc + 1 < NC) { issue(kc + 1, cur ^ 1); CP_COMMIT(); CP_WAIT1(); }
        else             { CP_WAIT0(); }
        __syncthreads();

        uint32_t sA = sb + cur * BUFSZ;
        uint32_t sB = sA + ATILE;
        #pragma unroll
        for (int ks = 0; ks < 4; ks++) {
            uint32_t av[4][4], bv[2][4];
            #pragma unroll
            for (int mt = 0; mt < 4; mt++) {
                uint32_t ad = sA + (wm*64 + mt*16 + a_row) * RSTRIDE + ((ks*2 + a_cs) << 4);
                LDSM4(av[mt][0], av[mt][1], av[mt][2], av[mt][3], ad);
            }
            #pragma unroll
            for (int bt = 0; bt < 2; bt++) {
                uint32_t bd = sB + (wn*32 + bt*16 + b_row) * RSTRIDE + ((ks*2 + b_cs) << 4);
                LDSM4(bv[bt][0], bv[bt][1], bv[bt][2], bv[bt][3], bd);
            }
            #pragma unroll
            for (int mt = 0; mt < 4; mt++)
                #pragma unroll
                for (int nt = 0; nt < 4; nt++) {
                    uint32_t b0 = bv[nt >> 1][(nt & 1) * 2];
                    uint32_t b1 = bv[nt >> 1][(nt & 1) * 2 + 1];
                    MMA16816(acc[mt][nt], av[mt], b0, b1);
                }
        }
        __syncthreads();
    }

    // ---- epilogue ----
    if (bias) bias += (size_t)z * (size_t)sbias;
    #pragma unroll
    for (int mt = 0; mt < 4; mt++) {
        int r0 = m0 + wm*64 + mt*16 + (lane >> 2);
        #pragma unroll
        for (int nt = 0; nt < 4; nt++) {
            int col = n0 + wn*32 + nt*8 + (lane & 3)*2;
            float bb0 = 0.f, bb1 = 0.f;
            if (bias) { bb0 = bias[col]; bb1 = bias[col+1]; }
            #pragma unroll
            for (int half_ = 0; half_ < 2; half_++) {
                int r = r0 + half_*8;
                if (r >= M) continue;
                float v0 = acc[mt][nt][half_*2]   * oscale + bb0;
                float v1 = acc[mt][nt][half_*2+1] * oscale + bb1;
                if (ACT == 1) { v0 = gelu_exact(v0); v1 = gelu_exact(v1); }
                if (OMODE == 0) {
                    *(float2*)(C + (size_t)r*ldc + col) = make_float2(v0, v1);
                } else {
                    __half* d = C2 + (size_t)r*ldc + col;
                    __half h0 = __float2half_rn(v0);
                    __half h1 = __float2half_rn(v1);
                    __half l0 = __float2half_rn(v0 - __half2float(h0));
                    __half l1 = __float2half_rn(v1 - __half2float(h1));
                    *(__half2*)(d)          = __halves2half2(h0, h1);
                    *(__half2*)(d + segoff) = __halves2half2(l0, l1);
                }
            }
        }
    }
}

// ================= split / misc small kernels =================
__global__ void split2_k(const float* __restrict__ src, __half* __restrict__ dst,
                         long long total, int C, float scale) {
    long long idx = (long long)blockIdx.x * 256 + threadIdx.x;
    if (idx >= total) return;
    long long r = idx / C; int c = (int)(idx % C);
    float v = src[idx] * scale;
    __half h = __float2half_rn(v);
    __half l = __float2half_rn(v - __half2float(h));
    __half* d = dst + r * (2LL*C) + c;
    d[0] = h; d[C] = l;
}

__global__ void biascat_k(const float* __restrict__ bp, const float* __restrict__ ipb) {
    int i = blockIdx.x * 256 + threadIdx.x;
    if (i < DD)      g_bc[i] = bp[i];
    else if (i < XQ) g_bc[i] = ipb[i - DD];
}

__global__ void norm_k() {
    int r = blockIdx.x;
    const float* p = g_xq + (size_t)r * XQ;
    float ss = 0.f;
    for (int i = threadIdx.x; i < DD; i += 256) { float v = p[i]; ss += v*v; }
    __shared__ float sh[256];
    sh[threadIdx.x] = ss; __syncthreads();
    for (int o = 128; o > 0; o >>= 1) {
        if (threadIdx.x < o) sh[threadIdx.x] += sh[threadIdx.x + o];
        __syncthreads();
    }
    if (threadIdx.x == 0) g_norm[r] = fmaxf(sqrtf(sh[0]), 1e-8f);
}

__global__ void cos_k() {
    int b = blockIdx.y, t = blockIdx.x;
    int scale, i;
    if (t < 1023)      { scale = 1; i = t; }
    else if (t < 1534) { scale = 2; i = t - 1023; }
    else               { scale = 4; i = t - 1534; }
    int s0 = i * scale, s1 = s0 + scale;
    const float* a = g_xq + ((size_t)b*SS + s0) * XQ;
    const float* c = g_xq + ((size_t)b*SS + s1) * XQ;
    float d = 0.f;
    for (int j = threadIdx.x; j < DD; j += 256) d += a[j] * c[j];
    __shared__ float sh[256];
    sh[threadIdx.x] = d; __syncthreads();
    for (int o = 128; o > 0; o >>= 1) {
        if (threadIdx.x < o) sh[threadIdx.x] += sh[threadIdx.x + o];
        __syncthreads();
    }
    if (threadIdx.x == 0)
        g_cs[b*CS_TOT + t] = sh[0] / (g_norm[b*SS + s0] * g_norm[b*SS + s1]);
}

__global__ void base_k() {
    int idx = blockIdx.x * 256 + threadIdx.x;
    if (idx >= NB*SM1) return;
    int b = idx / SM1, j = idx % SM1;
    const int Ls[3]   = {1023, 511, 255};
    const int offs[3] = {0, 1023, 1534};
    float acc = 0.f;
    #pragma unroll
    for (int u = 0; u < 3; u++) {
        int L = Ls[u];
        float ratio = (float)((double)L / 1023.0);
        float src = ((float)j + 0.5f) * ratio - 0.5f;
        src = fminf(fmaxf(src, 0.0f), (float)(L - 1));
        int i0 = (int)floorf(src);
        int i1 = min(i0 + 1, L - 1);
        float w = src - (float)i0;
        const float* cs = g_cs + b*CS_TOT + offs[u];
        acc += cs[i0] * (1.0f - w) + cs[i1] * w;
    }
    g_base[idx] = 0.5f * (1.0f - acc / 3.0f);
}

__global__ void learned_final_k(const float* __restrict__ detW3,
                                const float* __restrict__ detb3) {
    int r = blockIdx.x;
    __shared__ float sh[256];
    __shared__ float sacc;
    if (threadIdx.x == 0) sacc = 0.f;
    for (int n = 0; n < 3; n++) {
        const float* h2p = g_h2 + ((size_t)n*ROWS_DET + r) * (DD/2);
        const float* w   = detW3 + n*(DD/2);
        float part = 0.f;
        for (int j = threadIdx.x; j < DD/2; j += 256) part += h2p[j] * w[j];
        __syncthreads();
        sh[threadIdx.x] = part; __syncthreads();
        for (int o = 128; o > 0; o >>= 1) {
            if (threadIdx.x < o) sh[threadIdx.x] += sh[threadIdx.x + o];
            __syncthreads();
        }
        if (threadIdx.x == 0) {
            float t = sh[0] + detb3[n];
            sacc += 1.0f / (1.0f + expf(-t));
        }
        __syncthreads();
    }
    if (threadIdx.x == 0)
        g_final[r] = 0.6f * g_base[r] + 0.4f * (sacc / 3.0f);
}

// parallel segmentation: integer scans (exact, order-independent)
__global__ void __launch_bounds__(SS)
seg_scan_k() {
    int b = blockIdx.x, t = threadIdx.x;
    __shared__ int sscan[SS];
    __shared__ int smax[SS];
    __shared__ int rmin[SS];
    float bv = (t == 0) ? 1.0f : g_final[b*SM1 + t - 1];
    int f = (t == 0) ? 1 : (bv > 0.5f ? 1 : 0);
    sscan[t] = f;
    smax[t]  = f ? t : -1;
    rmin[t]  = f ? t : SS;
    __syncthreads();
    for (int o = 1; o < SS; o <<= 1) {
        int vs = sscan[t];
        int vm = smax[t];
        int vr = rmin[t];
        int vs2 = (t >= o) ? sscan[t - o] : 0;
        int vm2 = (t >= o) ? smax[t - o]  : -1;
        int vr2 = (t + o < SS) ? rmin[t + o] : SS;
        __syncthreads();
        sscan[t] = vs + vs2;
        smax[t]  = max(vm, vm2);
        rmin[t]  = min(vr, vr2);
        __syncthreads();
    }
    int m = sscan[t] - 1;
    g_seg[b*SS + t] = m;
    g_qlo[b*SS + t] = smax[t];
    int hi = (t < SS - 1) ? rmin[t + 1] : SS;
    g_qhi[b*SS + t] = hi;
    if (t < MAXC) { g_segstart[b*MAXC + t] = 0; g_segcount[b*MAXC + t] = 0; }
    __syncthreads();
    if (f && m < MAXC) {
        g_segstart[b*MAXC + m] = t;
        g_segcount[b*MAXC + m] = hi - t;
    }
}

// fused segment attention: one warp per (b, s, h); fp32; writes fp16-split ctx
__global__ void __launch_bounds__(256)
seg_attn_k() {
    __shared__ float dots[8][SS];
    int w = threadIdx.x >> 5, lane = threadIdx.x & 31;
    int g = blockIdx.x * 8 + w;
    int h = g % NH;
    int s = (g / NH) & (SS - 1);
    int b = g / (NH * SS);
    int lo = g_qlo[b*SS + s], hi = g_qhi[b*SS + s];

    const float* qp = g_xq + ((size_t)(b*SS + s))*XQ + QOFF + h*HDIM + lane*4;
    float4 qv = *(const float4*)qp;
    const float scale = 0.088388347648318440550f;   // 1/sqrt(128)

    const float* kbase = g_xq + ((size_t)(b*SS))*XQ + QOFF + DD + h*HDIM + lane*4;
    float mx = -3.402823e38f;
    for (int k = lo; k < hi; k++) {
        float4 kv = *(const float4*)(kbase + (size_t)k*XQ);
        float d = qv.x*kv.x + qv.y*kv.y + qv.z*kv.z + qv.w*kv.w;
        #pragma unroll
        for (int o = 16; o > 0; o >>= 1) d += __shfl_xor_sync(0xffffffffu, d, o);
        d *= scale;
        if (lane == 0) dots[w][k - lo] = d;
        mx = fmaxf(mx, d);
    }
    __syncwarp();

    const float* vbase = g_xq + ((size_t)(b*SS))*XQ + QOFF + 2*DD + h*HDIM + lane*4;
    float4 acc = make_float4(0.f, 0.f, 0.f, 0.f);
    float sum = 0.f;
    for (int k = lo; k < hi; k++) {
        float e = expf(dots[w][k - lo] - mx);
        sum += e;
        float4 vv = *(const float4*)(vbase + (size_t)k*XQ);
        acc.x += e*vv.x; acc.y += e*vv.y; acc.z += e*vv.z; acc.w += e*vv.w;
    }
    float inv = 1.0f / sum;
    float c0 = acc.x*inv, c1 = acc.y*inv, c2 = acc.z*inv, c3 = acc.w*inv;

    __half* d = g_ctx2 + ((size_t)(b*SS + s))*(2*DD) + h*HDIM + lane*4;
    __half h0 = __float2half_rn(c0), h1 = __float2half_rn(c1);
    __half h2 = __float2half_rn(c2), h3 = __float2half_rn(c3);
    *(__half2*)(d)     = __halves2half2(h0, h1);
    *(__half2*)(d + 2) = __halves2half2(h2, h3);
    __half l0 = __float2half_rn(c0 - __half2float(h0));
    __half l1 = __float2half_rn(c1 - __half2float(h1));
    __half l2 = __float2half_rn(c2 - __half2float(h2));
    __half l3 = __float2half_rn(c3 - __half2float(h3));
    *(__half2*)(d + DD)     = __halves2half2(l0, l1);
    *(__half2*)(d + DD + 2) = __halves2half2(l2, l3);
}

// pooling + embeddings, writes 2-way fp16 split chunk directly
__global__ void chunk_k(const float* __restrict__ size_emb,
                        const float* __restrict__ pos_enc) {
    int m = blockIdx.x, b = blockIdx.y;
    int cnt = g_segcount[b*MAXC + m];
    int st  = g_segstart[b*MAXC + m];
    __half* drow = g_chunk2 + ((size_t)b*MAXC + m) * (2*DD);
    for (int d = threadIdx.x; d < DD; d += 256) {
        float v;
        if (cnt > 0) {
            float sum = 0.f;
            for (int s = st; s < st + cnt; s++)
                sum += g_attnout[((size_t)b*SS + s)*DD + d];
            int cl = min(cnt, 1023);
            v = sum / (float)cnt + size_emb[(size_t)cl*DD + d];
        } else v = 0.f;
        v += pos_enc[(size_t)m*DD + d];
        __half h = __float2half_rn(v);
        drow[d]      = h;
        drow[DD + d] = __float2half_rn(v - __half2float(h));
    }
}

__global__ void ln_k(const float* __restrict__ gamma,
                     const float* __restrict__ beta,
                     float* __restrict__ out) {
    int r = blockIdx.x;
    const float* y = g_y + (size_t)r*DD;
    __shared__ float sh[256];
    float s = 0.f;
    for (int d = threadIdx.x; d < DD; d += 256) s += y[d];
    sh[threadIdx.x] = s; __syncthreads();
    for (int o = 128; o > 0; o >>= 1) {
        if (threadIdx.x < o) sh[threadIdx.x] += sh[threadIdx.x+o];
        __syncthreads();
    }
    float mu = sh[0] / (float)DD; __syncthreads();
    float v2 = 0.f;
    for (int d = threadIdx.x; d < DD; d += 256) { float t = y[d]-mu; v2 += t*t; }
    sh[threadIdx.x] = v2; __syncthreads();
    for (int o = 128; o > 0; o >>= 1) {
        if (threadIdx.x < o) sh[threadIdx.x] += sh[threadIdx.x+o];
        __syncthreads();
    }
    float inv = 1.0f / sqrtf(sh[0] / (float)DD + 1e-5f);
    for (int d = threadIdx.x; d < DD; d += 256)
        out[(size_t)r*DD + d] = (y[d] - mu) * inv * gamma[d] + beta[d];
}

// ---------------- host launchers ----------------
struct GemmArgs {
    const __half *A, *B;
    const float* bias;
    float* C;
    __half* C2;
    int M, N, K, lda, ldb, ldc, segoff;
    float oscale;
    int npA, npB, splitN;
    long long sAi, sAo, sBi, sBo, sCi, sCo, sbias;
    int innerN, batch;
};

template<int ACT, int OMODE, int BIG>
static void tg_launch(const GemmArgs& a) {
    dim3 grid(a.N/128, (a.M + 127)/128, a.batch);
    tgemm_k<ACT,OMODE,BIG><<<grid,256,TG_SMEM>>>(a.A, a.B, a.bias, a.C, a.C2,
        a.M, a.K, a.lda, a.ldb, a.ldc, a.segoff, a.oscale,
        a.npA, a.npB, a.splitN,
        a.sAi, a.sAo, a.sBi, a.sBo, a.sCi, a.sCo, a.sbias, a.innerN);
}

static void split2(const float* src, __half* dst, long long rows, int cols, float scale) {
    long long total = rows * cols;
    split2_k<<<(unsigned)((total + 255)/256), 256>>>(src, dst, total, cols, scale);
}

#define NPALL 3, 3, (1<<30)

extern "C" void kernel_launch(void* const* d_in, const int* in_sizes, int n_in,
                              void* d_out, int out_size) {
    const float* x         = (const float*)d_in[0];
    const float* Wp        = (const float*)d_in[1];
    const float* bp        = (const float*)d_in[2];
    const float* detW1     = (const float*)d_in[3];
    const float* detb1     = (const float*)d_in[4];
    const float* detW2     = (const float*)d_in[5];
    const float* detb2     = (const float*)d_in[6];
    const float* detW3     = (const float*)d_in[7];
    const float* detb3     = (const float*)d_in[8];
    const float* in_proj_w = (const float*)d_in[9];
    const float* in_proj_b = (const float*)d_in[10];
    const float* out_w     = (const float*)d_in[11];
    const float* out_b     = (const float*)d_in[12];
    const float* size_emb  = (const float*)d_in[13];
    const float* pos_enc   = (const float*)d_in[14];
    const float* procW1    = (const float*)d_in[15];
    const float* procb1    = (const float*)d_in[16];
    const float* procW2    = (const float*)d_in[17];
    const float* procb2    = (const float*)d_in[18];
    const float* ln_g      = (const float*)d_in[19];
    const float* ln_b      = (const float*)d_in[20];
    float* outp = (float*)d_out;

    cudaFuncSetAttribute(tgemm_k<0,0,0>, cudaFuncAttributeMaxDynamicSharedMemorySize, TG_SMEM);
    cudaFuncSetAttribute(tgemm_k<1,0,0>, cudaFuncAttributeMaxDynamicSharedMemorySize, TG_SMEM);
    cudaFuncSetAttribute(tgemm_k<1,1,0>, cudaFuncAttributeMaxDynamicSharedMemorySize, TG_SMEM);
    cudaFuncSetAttribute(tgemm_k<1,1,1>, cudaFuncAttributeMaxDynamicSharedMemorySize, TG_SMEM);

    void *p;
    cudaGetSymbolAddress(&p, g_xq);      float* xq      = (float*)p;
    cudaGetSymbolAddress(&p, g_bc);      float* bc      = (float*)p;
    cudaGetSymbolAddress(&p, g_h2);      float* h2      = (float*)p;
    cudaGetSymbolAddress(&p, g_attnout); float* attnout = (float*)p;
    cudaGetSymbolAddress(&p, g_y);       float* yb      = (float*)p;
    cudaGetSymbolAddress(&p, g_x2);      __half* x2     = (__half*)p;
    cudaGetSymbolAddress(&p, g_wc2);     __half* wc2    = (__half*)p;
    cudaGetSymbolAddress(&p, g_dW1_2);   __half* dW1_2  = (__half*)p;
    cudaGetSymbolAddress(&p, g_h1_2);    __half* h1_2   = (__half*)p;
    cudaGetSymbolAddress(&p, g_dW2_2);   __half* dW2_2  = (__half*)p;
    cudaGetSymbolAddress(&p, g_ctx2);    __half* ctx2   = (__half*)p;
    cudaGetSymbolAddress(&p, g_outw2);   __half* outw2  = (__half*)p;
    cudaGetSymbolAddress(&p, g_chunk2);  __half* chunk2 = (__half*)p;
    cudaGetSymbolAddress(&p, g_pw1_2);   __half* pw1_2  = (__half*)p;
    cudaGetSymbolAddress(&p, g_hproc2);  __half* hproc2 = (__half*)p;
    cudaGetSymbolAddress(&p, g_pw2_2);   __half* pw2_2  = (__half*)p;

    // ===== input splits (weights scaled by 64 to keep fp16 lo plane normal) =====
    split2(x, x2, NB*SS, DD, 1.0f);
    split2(Wp, wc2, DD, DD, WSCALE);                          // rows 0..1535 of combined W
    split2(in_proj_w, wc2 + (size_t)DD*2*DD, 3*DD, DD, WSCALE); // rows 1536..6143
    split2(detW1, dW1_2, 3*DD, 2*DD, WSCALE);
    split2(detW2, dW2_2, 3*(DD/2), DD, WSCALE);
    split2(out_w, outw2, DD, DD, WSCALE);
    split2(procW1, pw1_2, 2*DD, DD, WSCALE);
    split2(procW2, pw2_2, DD, 2*DD, WSCALE);
    biascat_k<<<(XQ + 255)/256, 256>>>(bp, in_proj_b);

    // ===== merged xling|qkv GEMM: 3 products for n<1536 (boundary), 2 for qkv =====
    { GemmArgs a = { x2, wc2, bc, xq, nullptr, NB*SS, XQ, DD, 2*DD, 2*DD, XQ, 0,
                     OSINV, 3, 2, DD, 0,0,0,0,0,0,0, 1, 1 };
      tg_launch<0,0,0>(a); }

    // ===== boundary path =====
    norm_k<<<NB*SS, 256>>>();
    cos_k<<<dim3(CS_TOT, NB), 256>>>();
    base_k<<<(NB*SM1 + 255)/256, 256>>>();
    // h1 = gelu(bi @ detW1[n]^T + b) -> 2-way split directly; A gathered from x2 (BIG=1)
    { GemmArgs a = { x2, dW1_2, detb1, nullptr, h1_2, ROWS_DET, DD, 2*DD,
                     2*DD, 2*2*DD, 2*DD, DD, OSINV, NPALL,
                     0, 0, (long long)DD*2*2*DD, 0,
                     (long long)ROWS_DET*2*DD, 0, DD, 3, 3 };
      tg_launch<1,1,1>(a); }
    // h2 = gelu(h1 @ detW2[n]^T + b) fp32
    { GemmArgs a = { h1_2, dW2_2, detb2, h2, nullptr, ROWS_DET, DD/2, DD,
                     2*DD, 2*DD, DD/2, 0, OSINV, NPALL,
                     (long long)ROWS_DET*2*DD, 0, (long long)(DD/2)*2*DD, 0,
                     (long long)ROWS_DET*(DD/2), 0, DD/2, 3, 3 };
      tg_launch<1,0,0>(a); }
    learned_final_k<<<ROWS_DET, 256>>>(detW3, detb3);
    seg_scan_k<<<NB, SS>>>();

    // ===== continuous path =====
    // fused segment attention (fp32) -> ctx2 (fp16 split)
    seg_attn_k<<<NB*SS*NH/8, 256>>>();
    // attn_out = ctx @ out_w^T + out_b
    { GemmArgs a = { ctx2, outw2, out_b, attnout, nullptr, NB*SS, DD, DD,
                     2*DD, 2*DD, DD, 0, OSINV, NPALL, 0,0,0,0,0,0,0, 1, 1 };
      tg_launch<0,0,0>(a); }
    chunk_k<<<dim3(MAXC, NB), 256>>>(size_emb, pos_enc);
    // hproc = gelu(chunk @ procW1^T + b) -> 2-way split directly
    { GemmArgs a = { chunk2, pw1_2, procb1, nullptr, hproc2, NB*MAXC, 2*DD, DD,
                     2*DD, 2*DD, 2*2*DD, 2*DD, OSINV, NPALL, 0,0,0,0,0,0,0, 1, 1 };
      tg_launch<1,1,0>(a); }
    // y = hproc @ procW2^T + b
    { GemmArgs a = { hproc2, pw2_2, procb2, yb, nullptr, NB*MAXC, DD, 2*DD,
                     2*2*DD, 2*2*DD, DD, 0, OSINV, NPALL, 0,0,0,0,0,0,0, 1, 1 };
      tg_launch<0,0,0>(a); }
    ln_k<<<NB*MAXC, 256>>>(ln_g, ln_b, outp);
}